// round 6
// baseline (speedup 1.0000x reference)
#include <cuda_runtime.h>
#include <cuda_fp16.h>
#include <cstdint>
#include <cstddef>

#define NN 2048      // nodes
#define BB 16        // batch
#define TT 256       // time/feature dim
#define K3 (3*TT)    // 768  (sim / Y split K)
#define K2 (2*NN)    // 4096 (out split K)

// ---------------- device scratch (no allocations allowed) ----------------
__device__ float g_xavg[TT * NN];                 // [t][n]
__device__ float g_invn[NN];
__device__ __half g_xa3[(size_t)NN * K3];         // [n][768] = [h, l, h]
__device__ __half g_xb3[(size_t)NN * K3];         // [n][768] = [h, h, l]
__device__ __half g_w3[(size_t)TT * K3];          // [o][768] = [wh, wl, wh]
__device__ __half g_xT3[(size_t)BB * NN * K3];    // [b][n][768] = [xh, xh, xl]
__device__ unsigned char g_adj8[(size_t)NN * NN]; // directed adjacency 0/1
__device__ signed char g_nm8[(size_t)NN * NN];    // nmask 0/1 (s8)
__device__ float g_common[(size_t)NN * NN];       // exact integer counts
__device__ __half g_WT2[(size_t)NN * K2];         // [d][4096] = [M/128, M/16384]
__device__ __half g_Y2[(size_t)BB * TT * K2];     // [4096][4096] = [Yh, Yl*128]
__device__ float g_degp64[64 * NN];
__device__ float g_dinv[NN];
__device__ int g_maxi;

// ---------------- PTX helpers (sm_80-level features only) ----------------
__device__ __forceinline__ uint32_t smem_u32(const void* p) {
    uint32_t a;
    asm("{ .reg .u64 t; cvta.to.shared.u64 t, %1; cvt.u32.u64 %0, t; }"
        : "=r"(a) : "l"(p));
    return a;
}

#define CP16(dst, src) \
    asm volatile("cp.async.cg.shared.global [%0], [%1], 16;" :: "r"(dst), "l"(src))
#define CP_COMMIT() asm volatile("cp.async.commit_group;" ::: "memory")
#define CP_WAIT2()  asm volatile("cp.async.wait_group 2;" ::: "memory")

__device__ __forceinline__ void ldsm_x4(uint32_t& r0, uint32_t& r1, uint32_t& r2,
                                        uint32_t& r3, uint32_t addr) {
    asm volatile("ldmatrix.sync.aligned.m8n8.x4.shared.b16 {%0,%1,%2,%3}, [%4];"
                 : "=r"(r0), "=r"(r1), "=r"(r2), "=r"(r3) : "r"(addr));
}

__device__ __forceinline__ void mma16816(float* c, const uint32_t* a, const uint32_t* b) {
    asm volatile(
        "mma.sync.aligned.m16n8k16.row.col.f32.f16.f16.f32 "
        "{%0,%1,%2,%3}, {%4,%5,%6,%7}, {%8,%9}, {%0,%1,%2,%3};"
        : "+f"(c[0]), "+f"(c[1]), "+f"(c[2]), "+f"(c[3])
        : "r"(a[0]), "r"(a[1]), "r"(a[2]), "r"(a[3]), "r"(b[0]), "r"(b[1]));
}

__device__ __forceinline__ void mma16832s8(int* c, const uint32_t* a, const uint32_t* b) {
    asm volatile(
        "mma.sync.aligned.m16n8k32.row.col.s32.s8.s8.s32 "
        "{%0,%1,%2,%3}, {%4,%5,%6,%7}, {%8,%9}, {%0,%1,%2,%3};"
        : "+r"(c[0]), "+r"(c[1]), "+r"(c[2]), "+r"(c[3])
        : "r"(a[0]), "r"(a[1]), "r"(a[2]), "r"(a[3]), "r"(b[0]), "r"(b[1]));
}

// ---------------- small kernels ----------------
__global__ void k_init() { g_maxi = 0; }

__global__ void k_colmean(const float* __restrict__ x) {
    int e = blockIdx.x * blockDim.x + threadIdx.x;    // over T*N, [t][n]
    if (e >= TT * NN) return;
    float s = 0.f;
#pragma unroll
    for (int b = 0; b < BB; b++) s += x[(size_t)b * TT * NN + e];
    g_xavg[e] = s * (1.0f / BB);
}

__global__ void k_colnorm() {
    int n = blockIdx.x * blockDim.x + threadIdx.x;
    if (n >= NN) return;
    float s = 0.f;
#pragma unroll 4
    for (int t = 0; t < TT; t++) { float v = g_xavg[t * NN + n]; s = fmaf(v, v, s); }
    float nrm = sqrtf(s);
    g_invn[n] = 1.0f / fmaxf(nrm, 1e-12f);
}

__global__ void k_writenorm() {   // grid (NN/32, TT/32), block (32,32)
    __shared__ float tile[32][33];
    int n0 = blockIdx.x * 32, t0 = blockIdx.y * 32;
    int tx = threadIdx.x, ty = threadIdx.y;
    tile[ty][tx] = g_xavg[(t0 + ty) * NN + n0 + tx] * g_invn[n0 + tx];
    __syncthreads();
    int n = n0 + ty, t = t0 + tx;
    float v = tile[tx][ty];
    __half h = __float2half_rn(v);
    __half l = __float2half_rn(v - __half2float(h));
    size_t base = (size_t)n * K3;
    g_xa3[base + t] = h; g_xa3[base + TT + t] = l; g_xa3[base + 2 * TT + t] = h;
    g_xb3[base + t] = h; g_xb3[base + TT + t] = h; g_xb3[base + 2 * TT + t] = l;
}

// weight [t][o] -> w3 [o][768] = [wh, wl, wh]
__global__ void k_w3(const float* __restrict__ w) {  // grid (8,8), block (32,32)
    __shared__ float tile[32][33];
    int o0 = blockIdx.x * 32, t0 = blockIdx.y * 32;
    int tx = threadIdx.x, ty = threadIdx.y;
    tile[ty][tx] = w[(t0 + ty) * TT + o0 + tx];
    __syncthreads();
    int o = o0 + ty, t = t0 + tx;
    float v = tile[tx][ty];
    __half h = __float2half_rn(v);
    __half l = __float2half_rn(v - __half2float(h));
    size_t base = (size_t)o * K3;
    g_w3[base + t] = h; g_w3[base + TT + t] = l; g_w3[base + 2 * TT + t] = h;
}

// x [b][t][n] -> xT3 [b][n][768] = [xh, xh, xl]
__global__ void k_xt3(const float* __restrict__ x) { // grid (NN/32, TT/32, BB), block (32,32)
    __shared__ float tile[32][33];
    int n0 = blockIdx.x * 32, t0 = blockIdx.y * 32, z = blockIdx.z;
    int tx = threadIdx.x, ty = threadIdx.y;
    tile[ty][tx] = x[(size_t)z * TT * NN + (t0 + ty) * NN + n0 + tx];
    __syncthreads();
    int n = n0 + ty, t = t0 + tx;
    float v = tile[tx][ty];
    __half h = __float2half_rn(v);
    __half l = __float2half_rn(v - __half2float(h));
    size_t base = ((size_t)z * NN + n) * K3;
    g_xT3[base + t] = h; g_xT3[base + TT + t] = h; g_xT3[base + 2 * TT + t] = l;
}

__global__ void k_nmask() {       // grid (64,64), block (32,32)
    __shared__ unsigned char tileT[32][33];
    int bi = blockIdx.y * 32, bj = blockIdx.x * 32;
    int tx = threadIdx.x, ty = threadIdx.y;
    tileT[ty][tx] = g_adj8[(size_t)(bj + ty) * NN + bi + tx];
    __syncthreads();
    int i = bi + ty, j = bj + tx;
    int a  = g_adj8[(size_t)i * NN + j];
    int at = tileT[tx][ty];
    int v = (a + at > 0) ? 1 : 0;
    if (i == j) v = 1;
    g_nm8[(size_t)i * NN + j] = (signed char)v;
}

// WT2[d][s] = [fp16(M/128), fp16(M/16384)] + fused deg partials over s-blocks
__global__ void k_wt2() {         // grid (64,64): x = s-tile, y = d-tile; block (32,32)
    __shared__ unsigned char tileA[32][33];
    int bs = blockIdx.x * 32, bd = blockIdx.y * 32;
    int tx = threadIdx.x, ty = threadIdx.y;
    tileA[ty][tx] = g_adj8[(size_t)(bs + ty) * NN + bd + tx];  // adj[s][d] tile
    __syncthreads();
    int d = bd + ty, s = bs + tx;
    float c = g_common[(size_t)d * NN + s];      // = common[s][d] (symmetric)
    float m = 0.f;
    if (tileA[tx][ty] != 0 && c > 1.0f) m = c * c;
    size_t base = (size_t)d * K2 + s;
    g_WT2[base]      = __float2half_rn(m * (1.0f / 128.0f));
    g_WT2[base + NN] = __float2half_rn(m * (1.0f / 16384.0f));
    // deg partial: sum over the 32 s-values in this block (one warp per d-row)
    float ms = m;
#pragma unroll
    for (int off = 16; off > 0; off >>= 1)
        ms += __shfl_down_sync(0xffffffffu, ms, off);
    if (tx == 0) g_degp64[blockIdx.x * NN + d] = ms;
}

__global__ void k_dinv() {
    int d = blockIdx.x * blockDim.x + threadIdx.x;
    if (d >= NN) return;
    float s = 0.f;
#pragma unroll
    for (int c = 0; c < 64; c++) s += g_degp64[c * NN + d];
    float deg = s / (float)g_maxi;
    g_dinv[d] = (deg > 0.f) ? rsqrtf(deg) : 0.f;
}

// ---------------- HMMA fp16 GEMM: 256x128 CTA tile, 8 warps of 64x64 ----------------
enum { HEPI_ADJ = 0, HEPI_OUT = 1, HEPI_Y2 = 2 };

#define A_BYTES 20480                // 256 rows * 80 B
#define B_BYTES 10240                // 128 rows * 80 B
#define STAGE_B (A_BYTES + B_BYTES)  // 30720
#define HSMEM_BYTES (4 * STAGE_B)    // 122880

template <int EPI>
__global__ void __launch_bounds__(256)
hmma_gemm(const __half* __restrict__ A, const __half* __restrict__ B,
          float* __restrict__ C, int K, int lda, int ldb, int ldc,
          size_t strideB, int rowsPerZ,
          const float* __restrict__ gumbel, const float* __restrict__ bias)
{
    extern __shared__ char dsm[];
    const int tid = threadIdx.x, lane = tid & 31, wid = tid >> 5;
    const int wm = (wid & 3) * 64;       // 4 m-bands of 64
    const int wn = (wid >> 2) * 64;      // 2 n-bands of 64
    const int m0 = blockIdx.y * 256, n0 = blockIdx.x * 128;
    const int rowbase = rowsPerZ * blockIdx.z;

    B += strideB * blockIdx.z;
    const uint32_t s0 = smem_u32(dsm);

    float acc[4][8][4];
#pragma unroll
    for (int i = 0; i < 4; i++)
#pragma unroll
        for (int j = 0; j < 8; j++)
#pragma unroll
            for (int q = 0; q < 4; q++) acc[i][j][q] = 0.f;

    const int nch = K >> 5;
    const int lr = tid >> 2, lu = tid & 3;   // 64 rows per pass, 16B unit
    const __half* gA = A + (size_t)(m0 + lr) * lda + lu * 8;
    const __half* gB = B + (size_t)(n0 + lr) * ldb + lu * 8;
    const uint32_t sm_off = lr * 80 + lu * 16;

#define ISSUE(c) do {                                                      \
        int _buf = (c) & 3;                                                \
        uint32_t _da = s0 + _buf * STAGE_B + sm_off;                       \
        uint32_t _db = _da + A_BYTES;                                      \
        const __half* _ga = gA + ((size_t)(c) << 5);                       \
        const __half* _gb = gB + ((size_t)(c) << 5);                       \
        CP16(_da, _ga);                                                    \
        CP16(_da + 64 * 80,  _ga + (size_t)64 * lda);                      \
        CP16(_da + 128 * 80, _ga + (size_t)128 * lda);                     \
        CP16(_da + 192 * 80, _ga + (size_t)192 * lda);                     \
        CP16(_db, _gb);                                                    \
        CP16(_db + 64 * 80,  _gb + (size_t)64 * ldb);                      \
        CP_COMMIT();                                                       \
    } while (0)

    ISSUE(0); ISSUE(1); ISSUE(2);

    for (int c = 0; c < nch; c++) {
        CP_WAIT2();
        __syncthreads();
        if (c + 3 < nch) ISSUE(c + 3);

        const uint32_t ba = s0 + (c & 3) * STAGE_B;
        const uint32_t bb = ba + A_BYTES;
#pragma unroll
        for (int k16 = 0; k16 < 2; k16++) {
            uint32_t a[4][4], b[8][2];
            {
                int arow = wm + (lane & 15);
                int au = k16 * 2 + (lane >> 4);
#pragma unroll
                for (int mt = 0; mt < 4; mt++)
                    ldsm_x4(a[mt][0], a[mt][1], a[mt][2], a[mt][3],
                            ba + (arow + mt * 16) * 80 + au * 16);
            }
#pragma unroll
            for (int np = 0; np < 4; np++) {
                int brow = wn + np * 16 + (lane & 7) + ((lane >> 4) << 3);
                int bu = k16 * 2 + ((lane >> 3) & 1);
                uint32_t r0, r1, r2, r3;
                ldsm_x4(r0, r1, r2, r3, bb + brow * 80 + bu * 16);
                b[2 * np][0] = r0; b[2 * np][1] = r1;
                b[2 * np + 1][0] = r2; b[2 * np + 1][1] = r3;
            }
#pragma unroll
            for (int mt = 0; mt < 4; mt++)
#pragma unroll
                for (int nt = 0; nt < 8; nt++)
                    mma16816(acc[mt][nt], a[mt], b[nt]);
        }
    }
#undef ISSUE

    // epilogue
    const int g = lane >> 2, tig = lane & 3;
#pragma unroll
    for (int mt = 0; mt < 4; mt++) {
#pragma unroll
        for (int half = 0; half < 2; half++) {
            int row = m0 + wm + mt * 16 + g + half * 8;
            int grow = rowbase + row;
#pragma unroll
            for (int nt = 0; nt < 8; nt++) {
                int col = n0 + wn + nt * 8 + 2 * tig;
                float v0 = acc[mt][nt][half * 2 + 0];
                float v1 = acc[mt][nt][half * 2 + 1];
                if (EPI == HEPI_ADJ) {
                    const float2* g2 = (const float2*)gumbel;
                    float2 ga = g2[(size_t)row * NN + col];
                    float2 gb = g2[(size_t)row * NN + col + 1];
                    float s0v = (v0 + 1.0f) * 0.5f;
                    float s1v = (v1 + 1.0f) * 0.5f;
                    uchar2 o;
                    o.x = (s0v + ga.x > (1.0f - s0v) + ga.y) ? 1 : 0;
                    o.y = (s1v + gb.x > (1.0f - s1v) + gb.y) ? 1 : 0;
                    *(uchar2*)&g_adj8[(size_t)row * NN + col] = o;
                } else if (EPI == HEPI_OUT) {
                    float sc = 128.0f / (float)g_maxi;
                    float bv = bias[row & (TT - 1)];
                    float2 o;
                    o.x = v0 * (g_dinv[col] * sc) + bv;
                    o.y = v1 * (g_dinv[col + 1] * sc) + bv;
                    *(float2*)&C[(size_t)row * ldc + col] = o;
                } else {  // HEPI_Y2: write [Yh, Yl*128] segments
                    float y0 = v0 * g_dinv[col];
                    float y1 = v1 * g_dinv[col + 1];
                    __half h0 = __float2half_rn(y0), h1 = __float2half_rn(y1);
                    float f0 = __half2float(h0), f1 = __half2float(h1);
                    size_t base = (size_t)grow * K2 + col;
                    __half2 seg0; seg0.x = h0; seg0.y = h1;
                    __half2 seg1; seg1.x = __float2half_rn((y0 - f0) * 128.0f);
                                  seg1.y = __float2half_rn((y1 - f1) * 128.0f);
                    *(__half2*)&g_Y2[base]      = seg0;
                    *(__half2*)&g_Y2[base + NN] = seg1;
                }
            }
        }
    }
}

// ---------------- int8 MMA GEMM for common = nm @ nm^T (exact) ----------------
#define I8_TILE_B 10240
#define I8_STAGE_B (2 * I8_TILE_B)
#define I8SMEM_BYTES (4 * I8_STAGE_B)    // 81920

__global__ void __launch_bounds__(256, 2)
i8gemm_common(const signed char* __restrict__ A, const signed char* __restrict__ B,
              float* __restrict__ C, int K, int lda, int ldb, int ldc)
{
    extern __shared__ char dsm[];
    const int tid = threadIdx.x, lane = tid & 31, wid = tid >> 5;
    const int wm = (wid & 3) * 32;
    const int wn = (wid >> 2) * 64;
    const int m0 = blockIdx.y * 128, n0 = blockIdx.x * 128;

    const uint32_t s0 = smem_u32(dsm);

    int acc[2][8][4];
#pragma unroll
    for (int i = 0; i < 2; i++)
#pragma unroll
        for (int j = 0; j < 8; j++)
#pragma unroll
            for (int q = 0; q < 4; q++) acc[i][j][q] = 0;

    const int nch = K >> 6;
    const int lr = tid >> 2, lu = tid & 3;
    const signed char* gA = A + (size_t)(m0 + lr) * lda + lu * 16;
    const signed char* gB = B + (size_t)(n0 + lr) * ldb + lu * 16;
    const uint32_t sm_off = lr * 80 + lu * 16;

#define ISSUE8(c) do {                                                     \
        int _buf = (c) & 3;                                                \
        uint32_t _da = s0 + _buf * I8_STAGE_B + sm_off;                    \
        uint32_t _db = _da + I8_TILE_B;                                    \
        const signed char* _ga = gA + ((size_t)(c) << 6);                  \
        const signed char* _gb = gB + ((size_t)(c) << 6);                  \
        CP16(_da, _ga); CP16(_db, _gb);                                    \
        CP16(_da + 64 * 80, _ga + (size_t)64 * lda);                       \
        CP16(_db + 64 * 80, _gb + (size_t)64 * ldb);                       \
        CP_COMMIT();                                                       \
    } while (0)

    ISSUE8(0); ISSUE8(1); ISSUE8(2);

    for (int c = 0; c < nch; c++) {
        CP_WAIT2();
        __syncthreads();
        if (c + 3 < nch) ISSUE8(c + 3);

        const uint32_t ba = s0 + (c & 3) * I8_STAGE_B;
        const uint32_t bb = ba + I8_TILE_B;
#pragma unroll
        for (int k32 = 0; k32 < 2; k32++) {
            uint32_t a[2][4], b[8][2];
            {
                int arow = wm + (lane & 15);
                int au = k32 * 2 + (lane >> 4);
                ldsm_x4(a[0][0], a[0][1], a[0][2], a[0][3], ba + arow * 80 + au * 16);
                ldsm_x4(a[1][0], a[1][1], a[1][2], a[1][3], ba + (arow + 16) * 80 + au * 16);
            }
#pragma unroll
            for (int np = 0; np < 4; np++) {
                int brow = wn + np * 16 + (lane & 7) + ((lane >> 4) << 3);
                int bu = k32 * 2 + ((lane >> 3) & 1);
                uint32_t r0, r1, r2, r3;
                ldsm_x4(r0, r1, r2, r3, bb + brow * 80 + bu * 16);
                b[2 * np][0] = r0; b[2 * np][1] = r1;
                b[2 * np + 1][0] = r2; b[2 * np + 1][1] = r3;
            }
#pragma unroll
            for (int mt = 0; mt < 2; mt++)
#pragma unroll
                for (int nt = 0; nt < 8; nt++)
                    mma16832s8(acc[mt][nt], a[mt], b[nt]);
        }
    }
#undef ISSUE8

    const int g = lane >> 2, tig = lane & 3;
    int lmax = 0;
#pragma unroll
    for (int mt = 0; mt < 2; mt++) {
#pragma unroll
        for (int half = 0; half < 2; half++) {
            int row = m0 + wm + mt * 16 + g + half * 8;
#pragma unroll
            for (int nt = 0; nt < 8; nt++) {
                int col = n0 + wn + nt * 8 + 2 * tig;
                int v0 = acc[mt][nt][half * 2 + 0];
                int v1 = acc[mt][nt][half * 2 + 1];
                float2 o; o.x = (float)v0; o.y = (float)v1;
                *(float2*)&C[(size_t)row * ldc + col] = o;
                lmax = max(lmax, max(v0, v1));
            }
        }
    }
    __syncthreads();
    int* red = (int*)dsm;
    red[tid] = lmax;
    __syncthreads();
    for (int s = 128; s > 0; s >>= 1) {
        if (tid < s) red[tid] = max(red[tid], red[tid + s]);
        __syncthreads();
    }
    if (tid == 0) atomicMax(&g_maxi, red[0]);
}

// ---------------- launcher ----------------
extern "C" void kernel_launch(void* const* d_in, const int* in_sizes, int n_in,
                              void* d_out, int out_size)
{
    const float* x      = (const float*)d_in[0];   // [B,T,N]
    const float* weight = (const float*)d_in[1];   // [T,T]
    const float* bias   = (const float*)d_in[2];   // [T]
    const float* gumbel = (const float*)d_in[3];   // [N*N, 2]
    float* out = (float*)d_out;                    // [B,T,N] = [4096][2048]

    __half *p_xa3, *p_xb3, *p_wt2, *p_y2, *p_w3, *p_xt3;
    signed char* p_nm8;
    float* p_common;
    cudaGetSymbolAddress((void**)&p_xa3,    g_xa3);
    cudaGetSymbolAddress((void**)&p_xb3,    g_xb3);
    cudaGetSymbolAddress((void**)&p_nm8,    g_nm8);
    cudaGetSymbolAddress((void**)&p_wt2,    g_WT2);
    cudaGetSymbolAddress((void**)&p_y2,     g_Y2);
    cudaGetSymbolAddress((void**)&p_w3,     g_w3);
    cudaGetSymbolAddress((void**)&p_xt3,    g_xT3);
    cudaGetSymbolAddress((void**)&p_common, g_common);

    cudaFuncSetAttribute(hmma_gemm<HEPI_ADJ>, cudaFuncAttributeMaxDynamicSharedMemorySize, HSMEM_BYTES);
    cudaFuncSetAttribute(hmma_gemm<HEPI_OUT>, cudaFuncAttributeMaxDynamicSharedMemorySize, HSMEM_BYTES);
    cudaFuncSetAttribute(hmma_gemm<HEPI_Y2>,  cudaFuncAttributeMaxDynamicSharedMemorySize, HSMEM_BYTES);
    cudaFuncSetAttribute(i8gemm_common,       cudaFuncAttributeMaxDynamicSharedMemorySize, I8SMEM_BYTES);

    k_init<<<1, 1>>>();

    // mean over batch + row-normalize + fp16 hi/lo split (K-concat)
    k_colmean<<<(TT * NN) / 256, 256>>>(x);
    k_colnorm<<<NN / 256, 256>>>();
    {
        dim3 grid(NN / 32, TT / 32); dim3 blk(32, 32);
        k_writenorm<<<grid, blk>>>();
    }
    {
        dim3 grid(TT / 32, TT / 32); dim3 blk(32, 32);
        k_w3<<<grid, blk>>>(weight);
    }
    {
        dim3 grid(NN / 32, TT / 32, BB); dim3 blk(32, 32);
        k_xt3<<<grid, blk>>>(x);
    }

    // sim GEMM (3-term fp16 split, K=768) fused gumbel argmax -> adj8
    {
        dim3 grid(NN / 128, NN / 256);
        hmma_gemm<HEPI_ADJ><<<grid, 256, HSMEM_BYTES>>>(
            p_xa3, p_xb3, nullptr, K3, K3, K3, 0, 0, 0, gumbel, nullptr);
    }

    // nmask (s8, 0/1)
    {
        dim3 grid(NN / 32, NN / 32); dim3 blk(32, 32);
        k_nmask<<<grid, blk>>>();
    }

    // common = nm @ nm^T, exact int8 MMA + global max (int atomic)
    {
        dim3 grid(NN / 128, NN / 128);
        i8gemm_common<<<grid, 256, I8SMEM_BYTES>>>(p_nm8, p_nm8, p_common, NN, NN, NN, NN);
    }

    // WT2 (2-segment fp16 of M^T) + fused deg partials
    {
        dim3 grid(NN / 32, NN / 32); dim3 blk(32, 32);
        k_wt2<<<grid, blk>>>();
    }
    k_dinv<<<NN / 256, 256>>>();

    // Y2 via HMMA: Y[(b,o)][n] = sum_t w3[o][k] * xT3[b][n][k], epi scales by dinv & 2-splits
    {
        dim3 grid(NN / 128, TT / 256, BB);   // (16, 1, 16)
        hmma_gemm<HEPI_Y2><<<grid, 256, HSMEM_BYTES>>>(
            p_w3, p_xt3, nullptr, K3, K3, K3, 0,
            (size_t)NN * K3, TT, nullptr, nullptr);
    }

    // out = (Y' @ M) * 128*dinv[d]/max + bias  (2-term fp16 K-concat, K=4096)
    {
        dim3 grid(NN / 128, (BB * TT) / 256);  // (16, 16)
        hmma_gemm<HEPI_OUT><<<grid, 256, HSMEM_BYTES>>>(
            p_y2, p_wt2, out, K2, K2, K2, NN, 0, 0, nullptr, bias);
    }
}

// round 7
// speedup vs baseline: 1.0517x; 1.0517x over previous
#include <cuda_runtime.h>
#include <cuda_fp16.h>
#include <cstdint>
#include <cstddef>

#define NN 2048      // nodes
#define BB 16        // batch
#define TT 256       // time/feature dim
#define K3 (3*TT)    // 768  (sim / Y split K)
#define K2 (2*NN)    // 4096 (out split K)

// ---------------- device scratch (no allocations allowed) ----------------
__device__ float g_xavg[TT * NN];                 // [t][n]
__device__ float g_invn[NN];
__device__ __half g_xa3[(size_t)NN * K3];         // [n][768] = [h, l, h]
__device__ __half g_xb3[(size_t)NN * K3];         // [n][768] = [h, h, l]
__device__ __half g_w3[(size_t)TT * K3];          // [o][768] = [wh, wl, wh]
__device__ __half g_xT3[(size_t)BB * NN * K3];    // [b][n][768] = [xh, xh, xl]
__device__ unsigned char g_adj8[(size_t)NN * NN]; // directed adjacency 0/1
__device__ signed char g_nm8[(size_t)NN * NN];    // nmask 0/1 (s8)
__device__ float g_common[(size_t)NN * NN];       // exact integer counts
__device__ __half g_WT2[(size_t)NN * K2];         // [d][4096] = [Wn^T, Wn^T/8]
__device__ __half g_Y2[(size_t)BB * TT * K2];     // [4096][4096] = [Yh, (Y-Yh)*8]
__device__ float g_degpart[16 * NN];
__device__ float g_dinv[NN];

// ---------------- PTX helpers (sm_80-level features only) ----------------
__device__ __forceinline__ uint32_t smem_u32(const void* p) {
    uint32_t a;
    asm("{ .reg .u64 t; cvta.to.shared.u64 t, %1; cvt.u32.u64 %0, t; }"
        : "=r"(a) : "l"(p));
    return a;
}

#define CP16(dst, src) \
    asm volatile("cp.async.cg.shared.global [%0], [%1], 16;" :: "r"(dst), "l"(src))
#define CP_COMMIT() asm volatile("cp.async.commit_group;" ::: "memory")
#define CP_WAIT2()  asm volatile("cp.async.wait_group 2;" ::: "memory")

__device__ __forceinline__ void ldsm_x4(uint32_t& r0, uint32_t& r1, uint32_t& r2,
                                        uint32_t& r3, uint32_t addr) {
    asm volatile("ldmatrix.sync.aligned.m8n8.x4.shared.b16 {%0,%1,%2,%3}, [%4];"
                 : "=r"(r0), "=r"(r1), "=r"(r2), "=r"(r3) : "r"(addr));
}

__device__ __forceinline__ void mma16816(float* c, const uint32_t* a, const uint32_t* b) {
    asm volatile(
        "mma.sync.aligned.m16n8k16.row.col.f32.f16.f16.f32 "
        "{%0,%1,%2,%3}, {%4,%5,%6,%7}, {%8,%9}, {%0,%1,%2,%3};"
        : "+f"(c[0]), "+f"(c[1]), "+f"(c[2]), "+f"(c[3])
        : "r"(a[0]), "r"(a[1]), "r"(a[2]), "r"(a[3]), "r"(b[0]), "r"(b[1]));
}

__device__ __forceinline__ void mma16832s8(int* c, const uint32_t* a, const uint32_t* b) {
    asm volatile(
        "mma.sync.aligned.m16n8k32.row.col.s32.s8.s8.s32 "
        "{%0,%1,%2,%3}, {%4,%5,%6,%7}, {%8,%9}, {%0,%1,%2,%3};"
        : "+r"(c[0]), "+r"(c[1]), "+r"(c[2]), "+r"(c[3])
        : "r"(a[0]), "r"(a[1]), "r"(a[2]), "r"(a[3]), "r"(b[0]), "r"(b[1]));
}

// ---------------- small kernels ----------------
__global__ void k_colmean(const float* __restrict__ x) {
    int e = blockIdx.x * blockDim.x + threadIdx.x;    // over T*N, [t][n]
    if (e >= TT * NN) return;
    float s = 0.f;
#pragma unroll
    for (int b = 0; b < BB; b++) s += x[(size_t)b * TT * NN + e];
    g_xavg[e] = s * (1.0f / BB);
}

__global__ void k_colnorm() {
    int n = blockIdx.x * blockDim.x + threadIdx.x;
    if (n >= NN) return;
    float s = 0.f;
#pragma unroll 4
    for (int t = 0; t < TT; t++) { float v = g_xavg[t * NN + n]; s = fmaf(v, v, s); }
    float nrm = sqrtf(s);
    g_invn[n] = 1.0f / fmaxf(nrm, 1e-12f);
}

__global__ void k_writenorm() {   // grid (NN/32, TT/32), block (32,32)
    __shared__ float tile[32][33];
    int n0 = blockIdx.x * 32, t0 = blockIdx.y * 32;
    int tx = threadIdx.x, ty = threadIdx.y;
    tile[ty][tx] = g_xavg[(t0 + ty) * NN + n0 + tx] * g_invn[n0 + tx];
    __syncthreads();
    int n = n0 + ty, t = t0 + tx;
    float v = tile[tx][ty];
    __half h = __float2half_rn(v);
    __half l = __float2half_rn(v - __half2float(h));
    size_t base = (size_t)n * K3;
    g_xa3[base + t] = h; g_xa3[base + TT + t] = l; g_xa3[base + 2 * TT + t] = h;
    g_xb3[base + t] = h; g_xb3[base + TT + t] = h; g_xb3[base + 2 * TT + t] = l;
}

// weight [t][o] -> w3 [o][768] = [wh, wl, wh]
__global__ void k_w3(const float* __restrict__ w) {  // grid (8,8), block (32,32)
    __shared__ float tile[32][33];
    int o0 = blockIdx.x * 32, t0 = blockIdx.y * 32;
    int tx = threadIdx.x, ty = threadIdx.y;
    tile[ty][tx] = w[(t0 + ty) * TT + o0 + tx];
    __syncthreads();
    int o = o0 + ty, t = t0 + tx;
    float v = tile[tx][ty];
    __half h = __float2half_rn(v);
    __half l = __float2half_rn(v - __half2float(h));
    size_t base = (size_t)o * K3;
    g_w3[base + t] = h; g_w3[base + TT + t] = l; g_w3[base + 2 * TT + t] = h;
}

// x [b][t][n] -> xT3 [b][n][768] = [xh, xh, xl]
__global__ void k_xt3(const float* __restrict__ x) { // grid (NN/32, TT/32, BB), block (32,32)
    __shared__ float tile[32][33];
    int n0 = blockIdx.x * 32, t0 = blockIdx.y * 32, z = blockIdx.z;
    int tx = threadIdx.x, ty = threadIdx.y;
    tile[ty][tx] = x[(size_t)z * TT * NN + (t0 + ty) * NN + n0 + tx];
    __syncthreads();
    int n = n0 + ty, t = t0 + tx;
    float v = tile[tx][ty];
    __half h = __float2half_rn(v);
    __half l = __float2half_rn(v - __half2float(h));
    size_t base = ((size_t)z * NN + n) * K3;
    g_xT3[base + t] = h; g_xT3[base + TT + t] = h; g_xT3[base + 2 * TT + t] = l;
}

__global__ void k_nmask() {       // grid (64,64), block (32,32)
    __shared__ unsigned char tileT[32][33];
    int bi = blockIdx.y * 32, bj = blockIdx.x * 32;
    int tx = threadIdx.x, ty = threadIdx.y;
    tileT[ty][tx] = g_adj8[(size_t)(bj + ty) * NN + bi + tx];
    __syncthreads();
    int i = bi + ty, j = bj + tx;
    int a  = g_adj8[(size_t)i * NN + j];
    int at = tileT[tx][ty];
    int v = (a + at > 0) ? 1 : 0;
    if (i == j) v = 1;
    g_nm8[(size_t)i * NN + j] = (signed char)v;
}

// deg partials: D[d] partial over 128 source rows; M = adj*(c>1)*c^2
__global__ void k_degpart() {
    int d = blockIdx.x * blockDim.x + threadIdx.x;
    int chunk = blockIdx.y;
    float s = 0.f;
    int s0 = chunk * 128;
#pragma unroll 4
    for (int r = 0; r < 128; r++) {
        size_t e = (size_t)(s0 + r) * NN + d;
        float c = g_common[e];
        if (g_adj8[e] != 0 && c > 1.0f) s += c * c;
    }
    g_degpart[chunk * NN + d] = s;
}

// dinv[d] = rsqrt(D_d); max_common cancels in Wn = M / sqrt(D_s * D_d)
__global__ void k_dinv() {
    int d = blockIdx.x * blockDim.x + threadIdx.x;
    if (d >= NN) return;
    float s = 0.f;
#pragma unroll
    for (int c = 0; c < 16; c++) s += g_degpart[c * NN + d];
    g_dinv[d] = (s > 0.f) ? rsqrtf(s) : 0.f;
}

// WT2[d][s] = [fp16(Wn^T), fp16(Wn^T/8)], Wn[s,d] = M * dinv[s] * dinv[d]
__global__ void k_wnT() {         // grid (64,64): x = s-tile, y = d-tile; block (32,32)
    __shared__ unsigned char tileA[32][33];
    int bs = blockIdx.x * 32, bd = blockIdx.y * 32;
    int tx = threadIdx.x, ty = threadIdx.y;
    tileA[ty][tx] = g_adj8[(size_t)(bs + ty) * NN + bd + tx];  // adj[s][d] tile
    __syncthreads();
    int d = bd + ty, s = bs + tx;
    float c = g_common[(size_t)d * NN + s];      // = common[s][d] (symmetric)
    float m = 0.f;
    if (tileA[tx][ty] != 0 && c > 1.0f) m = c * c;
    float wn = m * g_dinv[s] * g_dinv[d];
    size_t base = (size_t)d * K2 + s;
    g_WT2[base]      = __float2half_rn(wn);
    g_WT2[base + NN] = __float2half_rn(wn * 0.125f);
}

// ---------------- HMMA fp16 GEMM: 128x128 tile, 8 warps of 32x64, 4-stage ----------------
enum { HEPI_ADJ = 0, HEPI_OUT = 1, HEPI_Y2 = 2 };

#define TILE_B 10240                 // 128 rows * 80 B
#define STAGE_B (2 * TILE_B)
#define HSMEM_BYTES (4 * STAGE_B)    // 81920

template <int EPI>
__global__ void __launch_bounds__(256, 2)
hmma_gemm(const __half* __restrict__ A, const __half* __restrict__ B,
          float* __restrict__ C, int K, int lda, int ldb, int ldc,
          size_t strideB, int rowsPerZ,
          const float* __restrict__ gumbel, const float* __restrict__ bias)
{
    extern __shared__ char dsm[];
    const int tid = threadIdx.x, lane = tid & 31, wid = tid >> 5;
    const int wm = (wid & 3) * 32;
    const int wn = (wid >> 2) * 64;
    const int m0 = blockIdx.y * 128, n0 = blockIdx.x * 128;
    const int rowbase = rowsPerZ * blockIdx.z;

    B += strideB * blockIdx.z;
    const uint32_t s0 = smem_u32(dsm);

    float acc[2][8][4];
#pragma unroll
    for (int i = 0; i < 2; i++)
#pragma unroll
        for (int j = 0; j < 8; j++)
#pragma unroll
            for (int q = 0; q < 4; q++) acc[i][j][q] = 0.f;

    const int nch = K >> 5;
    const int lr = tid >> 2, lu = tid & 3;
    const __half* gA = A + (size_t)(m0 + lr) * lda + lu * 8;
    const __half* gB = B + (size_t)(n0 + lr) * ldb + lu * 8;
    const uint32_t sm_off = lr * 80 + lu * 16;

#define ISSUE(c) do {                                                      \
        int _buf = (c) & 3;                                                \
        uint32_t _da = s0 + _buf * STAGE_B + sm_off;                       \
        uint32_t _db = _da + TILE_B;                                       \
        const __half* _ga = gA + ((size_t)(c) << 5);                       \
        const __half* _gb = gB + ((size_t)(c) << 5);                       \
        CP16(_da, _ga); CP16(_db, _gb);                                    \
        CP16(_da + 64 * 80, _ga + (size_t)64 * lda);                       \
        CP16(_db + 64 * 80, _gb + (size_t)64 * ldb);                       \
        CP_COMMIT();                                                       \
    } while (0)

    ISSUE(0); ISSUE(1); ISSUE(2);

    for (int c = 0; c < nch; c++) {
        CP_WAIT2();
        __syncthreads();
        if (c + 3 < nch) ISSUE(c + 3);

        const uint32_t ba = s0 + (c & 3) * STAGE_B;
        const uint32_t bb = ba + TILE_B;
#pragma unroll
        for (int k16 = 0; k16 < 2; k16++) {
            uint32_t a[2][4], b[8][2];
            {
                int arow = wm + (lane & 15);
                int au = k16 * 2 + (lane >> 4);
                ldsm_x4(a[0][0], a[0][1], a[0][2], a[0][3], ba + arow * 80 + au * 16);
                ldsm_x4(a[1][0], a[1][1], a[1][2], a[1][3], ba + (arow + 16) * 80 + au * 16);
            }
#pragma unroll
            for (int np = 0; np < 4; np++) {
                int brow = wn + np * 16 + (lane & 7) + ((lane >> 4) << 3);
                int bu = k16 * 2 + ((lane >> 3) & 1);
                uint32_t r0, r1, r2, r3;
                ldsm_x4(r0, r1, r2, r3, bb + brow * 80 + bu * 16);
                b[2 * np][0] = r0; b[2 * np][1] = r1;
                b[2 * np + 1][0] = r2; b[2 * np + 1][1] = r3;
            }
#pragma unroll
            for (int mt = 0; mt < 2; mt++)
#pragma unroll
                for (int nt = 0; nt < 8; nt++)
                    mma16816(acc[mt][nt], a[mt], b[nt]);
        }
    }
#undef ISSUE

    // epilogue
    const int g = lane >> 2, tig = lane & 3;
#pragma unroll
    for (int mt = 0; mt < 2; mt++) {
#pragma unroll
        for (int half = 0; half < 2; half++) {
            int row = m0 + wm + mt * 16 + g + half * 8;
            int grow = rowbase + row;
#pragma unroll
            for (int nt = 0; nt < 8; nt++) {
                int col = n0 + wn + nt * 8 + 2 * tig;
                float v0 = acc[mt][nt][half * 2 + 0];
                float v1 = acc[mt][nt][half * 2 + 1];
                if (EPI == HEPI_ADJ) {
                    const float2* g2 = (const float2*)gumbel;
                    float2 ga = g2[(size_t)row * NN + col];
                    float2 gb = g2[(size_t)row * NN + col + 1];
                    float s0v = (v0 + 1.0f) * 0.5f;
                    float s1v = (v1 + 1.0f) * 0.5f;
                    uchar2 o;
                    o.x = (s0v + ga.x > (1.0f - s0v) + ga.y) ? 1 : 0;
                    o.y = (s1v + gb.x > (1.0f - s1v) + gb.y) ? 1 : 0;
                    *(uchar2*)&g_adj8[(size_t)row * NN + col] = o;
                } else if (EPI == HEPI_OUT) {
                    float bv = bias[row & (TT - 1)];
                    float2 o;
                    o.x = v0 + bv;
                    o.y = v1 + bv;
                    *(float2*)&C[(size_t)row * ldc + col] = o;
                } else {  // HEPI_Y2: write [Yh, (Y-Yh)*8] segments (no dinv!)
                    __half h0 = __float2half_rn(v0), h1 = __float2half_rn(v1);
                    float f0 = __half2float(h0), f1 = __half2float(h1);
                    size_t base = (size_t)grow * K2 + col;
                    __half2 seg0; seg0.x = h0; seg0.y = h1;
                    __half2 seg1; seg1.x = __float2half_rn((v0 - f0) * 8.0f);
                                  seg1.y = __float2half_rn((v1 - f1) * 8.0f);
                    *(__half2*)&g_Y2[base]      = seg0;
                    *(__half2*)&g_Y2[base + NN] = seg1;
                }
            }
        }
    }
}

// ---------------- int8 MMA GEMM for common = nm @ nm^T (exact) ----------------
#define I8_TILE_B 10240
#define I8_STAGE_B (2 * I8_TILE_B)
#define I8SMEM_BYTES (4 * I8_STAGE_B)    // 81920

__global__ void __launch_bounds__(256, 2)
i8gemm_common(const signed char* __restrict__ A, const signed char* __restrict__ B,
              float* __restrict__ C, int K, int lda, int ldb, int ldc)
{
    extern __shared__ char dsm[];
    const int tid = threadIdx.x, lane = tid & 31, wid = tid >> 5;
    const int wm = (wid & 3) * 32;
    const int wn = (wid >> 2) * 64;
    const int m0 = blockIdx.y * 128, n0 = blockIdx.x * 128;

    const uint32_t s0 = smem_u32(dsm);

    int acc[2][8][4];
#pragma unroll
    for (int i = 0; i < 2; i++)
#pragma unroll
        for (int j = 0; j < 8; j++)
#pragma unroll
            for (int q = 0; q < 4; q++) acc[i][j][q] = 0;

    const int nch = K >> 6;
    const int lr = tid >> 2, lu = tid & 3;
    const signed char* gA = A + (size_t)(m0 + lr) * lda + lu * 16;
    const signed char* gB = B + (size_t)(n0 + lr) * ldb + lu * 16;
    const uint32_t sm_off = lr * 80 + lu * 16;

#define ISSUE8(c) do {                                                     \
        int _buf = (c) & 3;                                                \
        uint32_t _da = s0 + _buf * I8_STAGE_B + sm_off;                    \
        uint32_t _db = _da + I8_TILE_B;                                    \
        const signed char* _ga = gA + ((size_t)(c) << 6);                  \
        const signed char* _gb = gB + ((size_t)(c) << 6);                  \
        CP16(_da, _ga); CP16(_db, _gb);                                    \
        CP16(_da + 64 * 80, _ga + (size_t)64 * lda);                       \
        CP16(_db + 64 * 80, _gb + (size_t)64 * ldb);                       \
        CP_COMMIT();                                                       \
    } while (0)

    ISSUE8(0); ISSUE8(1); ISSUE8(2);

    for (int c = 0; c < nch; c++) {
        CP_WAIT2();
        __syncthreads();
        if (c + 3 < nch) ISSUE8(c + 3);

        const uint32_t ba = s0 + (c & 3) * I8_STAGE_B;
        const uint32_t bb = ba + I8_TILE_B;
#pragma unroll
        for (int k32 = 0; k32 < 2; k32++) {
            uint32_t a[2][4], b[8][2];
            {
                int arow = wm + (lane & 15);
                int au = k32 * 2 + (lane >> 4);
                ldsm_x4(a[0][0], a[0][1], a[0][2], a[0][3], ba + arow * 80 + au * 16);
                ldsm_x4(a[1][0], a[1][1], a[1][2], a[1][3], ba + (arow + 16) * 80 + au * 16);
            }
#pragma unroll
            for (int np = 0; np < 4; np++) {
                int brow = wn + np * 16 + (lane & 7) + ((lane >> 4) << 3);
                int bu = k32 * 2 + ((lane >> 3) & 1);
                uint32_t r0, r1, r2, r3;
                ldsm_x4(r0, r1, r2, r3, bb + brow * 80 + bu * 16);
                b[2 * np][0] = r0; b[2 * np][1] = r1;
                b[2 * np + 1][0] = r2; b[2 * np + 1][1] = r3;
            }
#pragma unroll
            for (int mt = 0; mt < 2; mt++)
#pragma unroll
                for (int nt = 0; nt < 8; nt++)
                    mma16832s8(acc[mt][nt], a[mt], b[nt]);
        }
    }
#undef ISSUE8

    const int g = lane >> 2, tig = lane & 3;
#pragma unroll
    for (int mt = 0; mt < 2; mt++) {
#pragma unroll
        for (int half = 0; half < 2; half++) {
            int row = m0 + wm + mt * 16 + g + half * 8;
#pragma unroll
            for (int nt = 0; nt < 8; nt++) {
                int col = n0 + wn + nt * 8 + 2 * tig;
                float2 o;
                o.x = (float)acc[mt][nt][half * 2 + 0];
                o.y = (float)acc[mt][nt][half * 2 + 1];
                *(float2*)&C[(size_t)row * ldc + col] = o;
            }
        }
    }
}

// ---------------- launcher ----------------
extern "C" void kernel_launch(void* const* d_in, const int* in_sizes, int n_in,
                              void* d_out, int out_size)
{
    const float* x      = (const float*)d_in[0];   // [B,T,N]
    const float* weight = (const float*)d_in[1];   // [T,T]
    const float* bias   = (const float*)d_in[2];   // [T]
    const float* gumbel = (const float*)d_in[3];   // [N*N, 2]
    float* out = (float*)d_out;                    // [B,T,N] = [4096][2048]

    __half *p_xa3, *p_xb3, *p_wt2, *p_y2, *p_w3, *p_xt3;
    signed char* p_nm8;
    float* p_common;
    cudaGetSymbolAddress((void**)&p_xa3,    g_xa3);
    cudaGetSymbolAddress((void**)&p_xb3,    g_xb3);
    cudaGetSymbolAddress((void**)&p_nm8,    g_nm8);
    cudaGetSymbolAddress((void**)&p_wt2,    g_WT2);
    cudaGetSymbolAddress((void**)&p_y2,     g_Y2);
    cudaGetSymbolAddress((void**)&p_w3,     g_w3);
    cudaGetSymbolAddress((void**)&p_xt3,    g_xT3);
    cudaGetSymbolAddress((void**)&p_common, g_common);

    cudaFuncSetAttribute(hmma_gemm<HEPI_ADJ>, cudaFuncAttributeMaxDynamicSharedMemorySize, HSMEM_BYTES);
    cudaFuncSetAttribute(hmma_gemm<HEPI_OUT>, cudaFuncAttributeMaxDynamicSharedMemorySize, HSMEM_BYTES);
    cudaFuncSetAttribute(hmma_gemm<HEPI_Y2>,  cudaFuncAttributeMaxDynamicSharedMemorySize, HSMEM_BYTES);
    cudaFuncSetAttribute(i8gemm_common,       cudaFuncAttributeMaxDynamicSharedMemorySize, I8SMEM_BYTES);

    // persistent side stream + events for fork-join capture (host handles only)
    static cudaStream_t sB = nullptr;
    static cudaEvent_t evFork = nullptr, evJoin = nullptr;
    if (sB == nullptr) {
        cudaStreamCreateWithFlags(&sB, cudaStreamNonBlocking);
        cudaEventCreateWithFlags(&evFork, cudaEventDisableTiming);
        cudaEventCreateWithFlags(&evJoin, cudaEventDisableTiming);
    }

    // ---- fork: Y chain on sB (depends only on inputs) ----
    cudaEventRecord(evFork, 0);
    cudaStreamWaitEvent(sB, evFork, 0);
    {
        dim3 grid(TT / 32, TT / 32); dim3 blk(32, 32);
        k_w3<<<grid, blk, 0, sB>>>(weight);
    }
    {
        dim3 grid(NN / 32, TT / 32, BB); dim3 blk(32, 32);
        k_xt3<<<grid, blk, 0, sB>>>(x);
    }
    {
        // Y[(b,o)][n] = sum_t w3[o][k] * xT3[b][n][k]; epilogue 2-splits (no dinv)
        dim3 grid(NN / 128, TT / 128, BB);
        hmma_gemm<HEPI_Y2><<<grid, 256, HSMEM_BYTES, sB>>>(
            p_w3, p_xt3, nullptr, K3, K3, K3, 0,
            (size_t)NN * K3, TT, nullptr, nullptr);
    }
    cudaEventRecord(evJoin, sB);

    // ---- adjacency chain on default stream ----
    k_colmean<<<(TT * NN) / 256, 256>>>(x);
    k_colnorm<<<NN / 256, 256>>>();
    {
        dim3 grid(NN / 32, TT / 32); dim3 blk(32, 32);
        k_writenorm<<<grid, blk>>>();
    }

    // sim GEMM (3-term fp16 split, K=768) fused gumbel argmax -> adj8
    {
        dim3 grid(NN / 128, NN / 128);
        hmma_gemm<HEPI_ADJ><<<grid, 256, HSMEM_BYTES>>>(
            p_xa3, p_xb3, nullptr, K3, K3, K3, 0, 0, 0, gumbel, nullptr);
    }

    // nmask (s8, 0/1)
    {
        dim3 grid(NN / 32, NN / 32); dim3 blk(32, 32);
        k_nmask<<<grid, blk>>>();
    }

    // common = nm @ nm^T, exact int8 MMA (no max needed: it cancels in Wn)
    {
        dim3 grid(NN / 128, NN / 128);
        i8gemm_common<<<grid, 256, I8SMEM_BYTES>>>(p_nm8, p_nm8, p_common, NN, NN, NN, NN);
    }

    // deg partials, dinv (raw sums; max cancels)
    {
        dim3 grid(NN / 256, 16);
        k_degpart<<<grid, 256>>>();
    }
    k_dinv<<<NN / 256, 256>>>();

    // WT2 = [fp16(Wn^T), fp16(Wn^T/8)]
    {
        dim3 grid(NN / 32, NN / 32); dim3 blk(32, 32);
        k_wnT<<<grid, blk>>>();
    }

    // ---- join: out GEMM needs g_Y2 (sB) + g_WT2 (default) ----
    cudaStreamWaitEvent(0, evJoin, 0);

    // out = Y @ Wn + bias  (2-term fp16 K-concat, K=4096)
    {
        dim3 grid(NN / 128, (BB * TT) / 128);
        hmma_gemm<HEPI_OUT><<<grid, 256, HSMEM_BYTES>>>(
            p_y2, p_wt2, out, K2, K2, K2, NN, 0, 0, nullptr, bias);
    }
}

// round 8
// speedup vs baseline: 1.2506x; 1.1891x over previous
#include <cuda_runtime.h>
#include <cuda_fp16.h>
#include <cstdint>
#include <cstddef>

#define NN 2048      // nodes
#define BB 16        // batch
#define TT 256       // time/feature dim
#define K3 (3*TT)    // 768  (sim / Y split K)
#define K2 (2*NN)    // 4096 (out split K)

// ---------------- device scratch (no allocations allowed) ----------------
__device__ float g_xavg[TT * NN];                 // [t][n]
__device__ float g_invn[NN];
__device__ __half g_xa3[(size_t)NN * K3];         // [n][768] = [h, l, h]
__device__ __half g_xb3[(size_t)NN * K3];         // [n][768] = [h, h, l]
__device__ __half g_w3[(size_t)TT * K3];          // [o][768] = [wh, wl, wh]
__device__ __half g_xT3[(size_t)BB * NN * K3];    // [b][n][768] = [xh, xh, xl]
__device__ unsigned char g_adj8[(size_t)NN * NN]; // directed adjacency 0/1
__device__ signed char g_nm8[(size_t)NN * NN];    // nmask 0/1 (s8)
__device__ float g_common[(size_t)NN * NN];       // exact integer counts
__device__ __half g_WT2[(size_t)NN * K2];         // [d][4096] = [Wn^T, Wn^T/8]
__device__ __half g_Y2[(size_t)BB * TT * K2];     // [4096][4096] = [Yh, (Y-Yh)*8]
__device__ float g_degpart[16 * NN];
__device__ float g_dinv[NN];

// ---------------- PTX helpers (sm_80-level features only) ----------------
__device__ __forceinline__ uint32_t smem_u32(const void* p) {
    uint32_t a;
    asm("{ .reg .u64 t; cvta.to.shared.u64 t, %1; cvt.u32.u64 %0, t; }"
        : "=r"(a) : "l"(p));
    return a;
}

#define CP16(dst, src) \
    asm volatile("cp.async.cg.shared.global [%0], [%1], 16;" :: "r"(dst), "l"(src))
#define CP_COMMIT() asm volatile("cp.async.commit_group;" ::: "memory")
#define CP_WAIT2()  asm volatile("cp.async.wait_group 2;" ::: "memory")

__device__ __forceinline__ void ldsm_x4(uint32_t& r0, uint32_t& r1, uint32_t& r2,
                                        uint32_t& r3, uint32_t addr) {
    asm volatile("ldmatrix.sync.aligned.m8n8.x4.shared.b16 {%0,%1,%2,%3}, [%4];"
                 : "=r"(r0), "=r"(r1), "=r"(r2), "=r"(r3) : "r"(addr));
}

__device__ __forceinline__ void mma16816(float* c, const uint32_t* a, const uint32_t* b) {
    asm volatile(
        "mma.sync.aligned.m16n8k16.row.col.f32.f16.f16.f32 "
        "{%0,%1,%2,%3}, {%4,%5,%6,%7}, {%8,%9}, {%0,%1,%2,%3};"
        : "+f"(c[0]), "+f"(c[1]), "+f"(c[2]), "+f"(c[3])
        : "r"(a[0]), "r"(a[1]), "r"(a[2]), "r"(a[3]), "r"(b[0]), "r"(b[1]));
}

__device__ __forceinline__ void mma16832s8(int* c, const uint32_t* a, const uint32_t* b) {
    asm volatile(
        "mma.sync.aligned.m16n8k32.row.col.s32.s8.s8.s32 "
        "{%0,%1,%2,%3}, {%4,%5,%6,%7}, {%8,%9}, {%0,%1,%2,%3};"
        : "+r"(c[0]), "+r"(c[1]), "+r"(c[2]), "+r"(c[3])
        : "r"(a[0]), "r"(a[1]), "r"(a[2]), "r"(a[3]), "r"(b[0]), "r"(b[1]));
}

// decode 1D lower-triangle index -> (bi >= bj)
__device__ __forceinline__ void tri_decode(int idx, int& bi, int& bj) {
    int b = (int)((sqrtf(8.0f * idx + 1.0f) - 1.0f) * 0.5f);
    while ((b + 1) * (b + 2) / 2 <= idx) b++;
    while (b * (b + 1) / 2 > idx) b--;
    bi = b;
    bj = idx - b * (b + 1) / 2;
}

// ---------------- small kernels ----------------
__global__ void k_colmean(const float* __restrict__ x) {
    int e = blockIdx.x * blockDim.x + threadIdx.x;    // over T*N, [t][n]
    if (e >= TT * NN) return;
    float s = 0.f;
#pragma unroll
    for (int b = 0; b < BB; b++) s += x[(size_t)b * TT * NN + e];
    g_xavg[e] = s * (1.0f / BB);
}

__global__ void k_colnorm() {
    int n = blockIdx.x * blockDim.x + threadIdx.x;
    if (n >= NN) return;
    float s = 0.f;
#pragma unroll 4
    for (int t = 0; t < TT; t++) { float v = g_xavg[t * NN + n]; s = fmaf(v, v, s); }
    float nrm = sqrtf(s);
    g_invn[n] = 1.0f / fmaxf(nrm, 1e-12f);
}

__global__ void k_writenorm() {   // grid (NN/32, TT/32), block (32,32)
    __shared__ float tile[32][33];
    int n0 = blockIdx.x * 32, t0 = blockIdx.y * 32;
    int tx = threadIdx.x, ty = threadIdx.y;
    tile[ty][tx] = g_xavg[(t0 + ty) * NN + n0 + tx] * g_invn[n0 + tx];
    __syncthreads();
    int n = n0 + ty, t = t0 + tx;
    float v = tile[tx][ty];
    __half h = __float2half_rn(v);
    __half l = __float2half_rn(v - __half2float(h));
    size_t base = (size_t)n * K3;
    g_xa3[base + t] = h; g_xa3[base + TT + t] = l; g_xa3[base + 2 * TT + t] = h;
    g_xb3[base + t] = h; g_xb3[base + TT + t] = h; g_xb3[base + 2 * TT + t] = l;
}

// weight [t][o] -> w3 [o][768] = [wh, wl, wh]
__global__ void k_w3(const float* __restrict__ w) {  // grid (8,8), block (32,32)
    __shared__ float tile[32][33];
    int o0 = blockIdx.x * 32, t0 = blockIdx.y * 32;
    int tx = threadIdx.x, ty = threadIdx.y;
    tile[ty][tx] = w[(t0 + ty) * TT + o0 + tx];
    __syncthreads();
    int o = o0 + ty, t = t0 + tx;
    float v = tile[tx][ty];
    __half h = __float2half_rn(v);
    __half l = __float2half_rn(v - __half2float(h));
    size_t base = (size_t)o * K3;
    g_w3[base + t] = h; g_w3[base + TT + t] = l; g_w3[base + 2 * TT + t] = h;
}

// x [b][t][n] -> xT3 [b][n][768] = [xh, xh, xl]
__global__ void k_xt3(const float* __restrict__ x) { // grid (NN/32, TT/32, BB), block (32,32)
    __shared__ float tile[32][33];
    int n0 = blockIdx.x * 32, t0 = blockIdx.y * 32, z = blockIdx.z;
    int tx = threadIdx.x, ty = threadIdx.y;
    tile[ty][tx] = x[(size_t)z * TT * NN + (t0 + ty) * NN + n0 + tx];
    __syncthreads();
    int n = n0 + ty, t = t0 + tx;
    float v = tile[tx][ty];
    __half h = __float2half_rn(v);
    __half l = __float2half_rn(v - __half2float(h));
    size_t base = ((size_t)z * NN + n) * K3;
    g_xT3[base + t] = h; g_xT3[base + TT + t] = h; g_xT3[base + 2 * TT + t] = l;
}

// deg partials: D[d] partial over 128 source rows; M = adj*(c>1)*c^2
__global__ void k_degpart() {
    int d = blockIdx.x * blockDim.x + threadIdx.x;
    int chunk = blockIdx.y;
    float s = 0.f;
    int s0 = chunk * 128;
#pragma unroll 4
    for (int r = 0; r < 128; r++) {
        size_t e = (size_t)(s0 + r) * NN + d;
        float c = g_common[e];
        if (g_adj8[e] != 0 && c > 1.0f) s += c * c;
    }
    g_degpart[chunk * NN + d] = s;
}

// dinv[d] = rsqrt(D_d); max_common cancels in Wn = M / sqrt(D_s * D_d)
__global__ void k_dinv() {
    int d = blockIdx.x * blockDim.x + threadIdx.x;
    if (d >= NN) return;
    float s = 0.f;
#pragma unroll
    for (int c = 0; c < 16; c++) s += g_degpart[c * NN + d];
    g_dinv[d] = (s > 0.f) ? rsqrtf(s) : 0.f;
}

// WT2[d][s] = [fp16(Wn^T), fp16(Wn^T/8)], Wn[s,d] = M * dinv[s] * dinv[d]
__global__ void k_wnT() {         // grid (64,64): x = s-tile, y = d-tile; block (32,32)
    __shared__ unsigned char tileA[32][33];
    int bs = blockIdx.x * 32, bd = blockIdx.y * 32;
    int tx = threadIdx.x, ty = threadIdx.y;
    tileA[ty][tx] = g_adj8[(size_t)(bs + ty) * NN + bd + tx];  // adj[s][d] tile
    __syncthreads();
    int d = bd + ty, s = bs + tx;
    float c = g_common[(size_t)d * NN + s];      // = common[s][d] (symmetric)
    float m = 0.f;
    if (tileA[tx][ty] != 0 && c > 1.0f) m = c * c;
    float wn = m * g_dinv[s] * g_dinv[d];
    size_t base = (size_t)d * K2 + s;
    g_WT2[base]      = __float2half_rn(wn);
    g_WT2[base + NN] = __float2half_rn(wn * 0.125f);
}

// ---------------- HMMA fp16 GEMM: 128x128 tile, 8 warps of 32x64, 4-stage ----------------
enum { HEPI_OUT = 1, HEPI_Y2 = 2 };

#define TILE_B 10240                 // 128 rows * 80 B
#define STAGE_B (2 * TILE_B)
#define HSMEM_BYTES (4 * STAGE_B)    // 81920

// mainloop body shared by all tensor kernels (A,B K-major, 80B pitch smem)
#define HMMA_MAINLOOP(ACCTYPE, MMAFN, KSHIFT, ELTSZ)                         \
    const int nch = K >> KSHIFT;                                             \
    const int lr = tid >> 2, lu = tid & 3;                                   \
    const uint32_t sm_off = lr * 80 + lu * 16;

template <int EPI>
__global__ void __launch_bounds__(256, 2)
hmma_gemm(const __half* __restrict__ A, const __half* __restrict__ B,
          float* __restrict__ C, int K, int lda, int ldb, int ldc,
          size_t strideB, int rowsPerZ,
          const float* __restrict__ bias)
{
    extern __shared__ char dsm[];
    const int tid = threadIdx.x, lane = tid & 31, wid = tid >> 5;
    const int wm = (wid & 3) * 32;
    const int wn = (wid >> 2) * 64;
    const int m0 = blockIdx.y * 128, n0 = blockIdx.x * 128;
    const int rowbase = rowsPerZ * blockIdx.z;

    B += strideB * blockIdx.z;
    const uint32_t s0 = smem_u32(dsm);

    float acc[2][8][4];
#pragma unroll
    for (int i = 0; i < 2; i++)
#pragma unroll
        for (int j = 0; j < 8; j++)
#pragma unroll
            for (int q = 0; q < 4; q++) acc[i][j][q] = 0.f;

    const int nch = K >> 5;
    const int lr = tid >> 2, lu = tid & 3;
    const __half* gA = A + (size_t)(m0 + lr) * lda + lu * 8;
    const __half* gB = B + (size_t)(n0 + lr) * ldb + lu * 8;
    const uint32_t sm_off = lr * 80 + lu * 16;

#define ISSUE(c) do {                                                      \
        int _buf = (c) & 3;                                                \
        uint32_t _da = s0 + _buf * STAGE_B + sm_off;                       \
        uint32_t _db = _da + TILE_B;                                       \
        const __half* _ga = gA + ((size_t)(c) << 5);                       \
        const __half* _gb = gB + ((size_t)(c) << 5);                       \
        CP16(_da, _ga); CP16(_db, _gb);                                    \
        CP16(_da + 64 * 80, _ga + (size_t)64 * lda);                       \
        CP16(_db + 64 * 80, _gb + (size_t)64 * ldb);                       \
        CP_COMMIT();                                                       \
    } while (0)

    ISSUE(0); ISSUE(1); ISSUE(2);

    for (int c = 0; c < nch; c++) {
        CP_WAIT2();
        __syncthreads();
        if (c + 3 < nch) ISSUE(c + 3);

        const uint32_t ba = s0 + (c & 3) * STAGE_B;
        const uint32_t bb = ba + TILE_B;
#pragma unroll
        for (int k16 = 0; k16 < 2; k16++) {
            uint32_t a[2][4], b[8][2];
            {
                int arow = wm + (lane & 15);
                int au = k16 * 2 + (lane >> 4);
                ldsm_x4(a[0][0], a[0][1], a[0][2], a[0][3], ba + arow * 80 + au * 16);
                ldsm_x4(a[1][0], a[1][1], a[1][2], a[1][3], ba + (arow + 16) * 80 + au * 16);
            }
#pragma unroll
            for (int np = 0; np < 4; np++) {
                int brow = wn + np * 16 + (lane & 7) + ((lane >> 4) << 3);
                int bu = k16 * 2 + ((lane >> 3) & 1);
                uint32_t r0, r1, r2, r3;
                ldsm_x4(r0, r1, r2, r3, bb + brow * 80 + bu * 16);
                b[2 * np][0] = r0; b[2 * np][1] = r1;
                b[2 * np + 1][0] = r2; b[2 * np + 1][1] = r3;
            }
#pragma unroll
            for (int mt = 0; mt < 2; mt++)
#pragma unroll
                for (int nt = 0; nt < 8; nt++)
                    mma16816(acc[mt][nt], a[mt], b[nt]);
        }
    }
#undef ISSUE

    const int g = lane >> 2, tig = lane & 3;
#pragma unroll
    for (int mt = 0; mt < 2; mt++) {
#pragma unroll
        for (int half = 0; half < 2; half++) {
            int row = m0 + wm + mt * 16 + g + half * 8;
            int grow = rowbase + row;
#pragma unroll
            for (int nt = 0; nt < 8; nt++) {
                int col = n0 + wn + nt * 8 + 2 * tig;
                float v0 = acc[mt][nt][half * 2 + 0];
                float v1 = acc[mt][nt][half * 2 + 1];
                if (EPI == HEPI_OUT) {
                    float bv = bias[row & (TT - 1)];
                    float2 o;
                    o.x = v0 + bv;
                    o.y = v1 + bv;
                    *(float2*)&C[(size_t)row * ldc + col] = o;
                } else {  // HEPI_Y2: write [Yh, (Y-Yh)*8] segments
                    __half h0 = __float2half_rn(v0), h1 = __float2half_rn(v1);
                    float f0 = __half2float(h0), f1 = __half2float(h1);
                    size_t base = (size_t)grow * K2 + col;
                    __half2 seg0; seg0.x = h0; seg0.y = h1;
                    __half2 seg1; seg1.x = __float2half_rn((v0 - f0) * 8.0f);
                                  seg1.y = __float2half_rn((v1 - f1) * 8.0f);
                    *(__half2*)&g_Y2[base]      = seg0;
                    *(__half2*)&g_Y2[base + NN] = seg1;
                }
            }
        }
    }
}

// ---------------- symmetric sim GEMM: lower-tri grid, fused adj + nmask ----------------
__global__ void __launch_bounds__(256, 2)
hmma_sim(const __half* __restrict__ A, const __half* __restrict__ B,
         const float* __restrict__ gumbel)
{
    extern __shared__ char dsm[];
    const int tid = threadIdx.x, lane = tid & 31, wid = tid >> 5;
    const int wm = (wid & 3) * 32;
    const int wn = (wid >> 2) * 64;
    int bi, bj;
    tri_decode(blockIdx.x, bi, bj);
    const int m0 = bi * 128, n0 = bj * 128;
    const int K = K3, lda = K3, ldb = K3;

    const uint32_t s0 = smem_u32(dsm);

    float acc[2][8][4];
#pragma unroll
    for (int i = 0; i < 2; i++)
#pragma unroll
        for (int j = 0; j < 8; j++)
#pragma unroll
            for (int q = 0; q < 4; q++) acc[i][j][q] = 0.f;

    const int nch = K >> 5;
    const int lr = tid >> 2, lu = tid & 3;
    const __half* gA = A + (size_t)(m0 + lr) * lda + lu * 8;
    const __half* gB = B + (size_t)(n0 + lr) * ldb + lu * 8;
    const uint32_t sm_off = lr * 80 + lu * 16;

#define ISSUE(c) do {                                                      \
        int _buf = (c) & 3;                                                \
        uint32_t _da = s0 + _buf * STAGE_B + sm_off;                       \
        uint32_t _db = _da + TILE_B;                                       \
        const __half* _ga = gA + ((size_t)(c) << 5);                       \
        const __half* _gb = gB + ((size_t)(c) << 5);                       \
        CP16(_da, _ga); CP16(_db, _gb);                                    \
        CP16(_da + 64 * 80, _ga + (size_t)64 * lda);                       \
        CP16(_db + 64 * 80, _gb + (size_t)64 * ldb);                       \
        CP_COMMIT();                                                       \
    } while (0)

    ISSUE(0); ISSUE(1); ISSUE(2);

    for (int c = 0; c < nch; c++) {
        CP_WAIT2();
        __syncthreads();
        if (c + 3 < nch) ISSUE(c + 3);

        const uint32_t ba = s0 + (c & 3) * STAGE_B;
        const uint32_t bb = ba + TILE_B;
#pragma unroll
        for (int k16 = 0; k16 < 2; k16++) {
            uint32_t a[2][4], b[8][2];
            {
                int arow = wm + (lane & 15);
                int au = k16 * 2 + (lane >> 4);
                ldsm_x4(a[0][0], a[0][1], a[0][2], a[0][3], ba + arow * 80 + au * 16);
                ldsm_x4(a[1][0], a[1][1], a[1][2], a[1][3], ba + (arow + 16) * 80 + au * 16);
            }
#pragma unroll
            for (int np = 0; np < 4; np++) {
                int brow = wn + np * 16 + (lane & 7) + ((lane >> 4) << 3);
                int bu = k16 * 2 + ((lane >> 3) & 1);
                uint32_t r0, r1, r2, r3;
                ldsm_x4(r0, r1, r2, r3, bb + brow * 80 + bu * 16);
                b[2 * np][0] = r0; b[2 * np][1] = r1;
                b[2 * np + 1][0] = r2; b[2 * np + 1][1] = r3;
            }
#pragma unroll
            for (int mt = 0; mt < 2; mt++)
#pragma unroll
                for (int nt = 0; nt < 8; nt++)
                    mma16816(acc[mt][nt], a[mt], b[nt]);
        }
    }
#undef ISSUE

    // epilogue: adj both orientations + nmask, staged in smem for coalesced stores
    __syncthreads();   // all warps done with pipeline smem
    unsigned char* adjS = (unsigned char*)dsm;
    unsigned char* adjT = (unsigned char*)dsm + 16384;
    signed char*   nmS  = (signed char*)(dsm + 32768);
    signed char*   nmT  = (signed char*)(dsm + 49152);
    const float2* g2 = (const float2*)gumbel;
    const int g = lane >> 2, tig = lane & 3;
#pragma unroll
    for (int mt = 0; mt < 2; mt++) {
#pragma unroll
        for (int half = 0; half < 2; half++) {
            int r_loc = wm + mt * 16 + g + half * 8;
            int row = m0 + r_loc;
#pragma unroll
            for (int nt = 0; nt < 8; nt++) {
#pragma unroll
                for (int e = 0; e < 2; e++) {
                    int c_loc = wn + nt * 8 + 2 * tig + e;
                    int col = n0 + c_loc;
                    float v = acc[mt][nt][half * 2 + e];
                    float s = (v + 1.0f) * 0.5f;
                    float2 grc = g2[(size_t)row * NN + col];
                    float2 gcr = g2[(size_t)col * NN + row];
                    unsigned char arc = (s + grc.x > (1.0f - s) + grc.y) ? 1 : 0;
                    unsigned char acr = (s + gcr.x > (1.0f - s) + gcr.y) ? 1 : 0;
                    signed char nm = (row == col) ? 1 : (signed char)((arc | acr) ? 1 : 0);
                    adjS[r_loc * 128 + c_loc] = arc;
                    adjT[c_loc * 128 + r_loc] = acr;
                    nmS[r_loc * 128 + c_loc] = nm;
                    nmT[c_loc * 128 + r_loc] = nm;
                }
            }
        }
    }
    __syncthreads();
    for (int i = tid; i < 1024; i += 256) {
        int r = i >> 3, u = i & 7;
        *(uint4*)&g_adj8[(size_t)(m0 + r) * NN + n0 + u * 16] = *(const uint4*)(adjS + r * 128 + u * 16);
        *(uint4*)&g_adj8[(size_t)(n0 + r) * NN + m0 + u * 16] = *(const uint4*)(adjT + r * 128 + u * 16);
        *(uint4*)&g_nm8 [(size_t)(m0 + r) * NN + n0 + u * 16] = *(const uint4*)(nmS  + r * 128 + u * 16);
        *(uint4*)&g_nm8 [(size_t)(n0 + r) * NN + m0 + u * 16] = *(const uint4*)(nmT  + r * 128 + u * 16);
    }
}

// ---------------- int8 MMA GEMM, symmetric: common = nm @ nm^T (exact) ----------------
#define I8_TILE_B 10240
#define I8_STAGE_B (2 * I8_TILE_B)
#define I8SMEM_BYTES (4 * I8_STAGE_B)    // 81920

__global__ void __launch_bounds__(256, 2)
i8gemm_common(const signed char* __restrict__ A, const signed char* __restrict__ B,
              float* __restrict__ C, int K, int lda, int ldb, int ldc)
{
    extern __shared__ char dsm[];
    const int tid = threadIdx.x, lane = tid & 31, wid = tid >> 5;
    const int wm = (wid & 3) * 32;
    const int wn = (wid >> 2) * 64;
    int bi, bj;
    tri_decode(blockIdx.x, bi, bj);
    const int m0 = bi * 128, n0 = bj * 128;

    const uint32_t s0 = smem_u32(dsm);

    int acc[2][8][4];
#pragma unroll
    for (int i = 0; i < 2; i++)
#pragma unroll
        for (int j = 0; j < 8; j++)
#pragma unroll
            for (int q = 0; q < 4; q++) acc[i][j][q] = 0;

    const int nch = K >> 6;
    const int lr = tid >> 2, lu = tid & 3;
    const signed char* gA = A + (size_t)(m0 + lr) * lda + lu * 16;
    const signed char* gB = B + (size_t)(n0 + lr) * ldb + lu * 16;
    const uint32_t sm_off = lr * 80 + lu * 16;

#define ISSUE8(c) do {                                                     \
        int _buf = (c) & 3;                                                \
        uint32_t _da = s0 + _buf * I8_STAGE_B + sm_off;                    \
        uint32_t _db = _da + I8_TILE_B;                                    \
        const signed char* _ga = gA + ((size_t)(c) << 6);                  \
        const signed char* _gb = gB + ((size_t)(c) << 6);                  \
        CP16(_da, _ga); CP16(_db, _gb);                                    \
        CP16(_da + 64 * 80, _ga + (size_t)64 * lda);                       \
        CP16(_db + 64 * 80, _gb + (size_t)64 * ldb);                       \
        CP_COMMIT();                                                       \
    } while (0)

    ISSUE8(0); ISSUE8(1); ISSUE8(2);

    for (int c = 0; c < nch; c++) {
        CP_WAIT2();
        __syncthreads();
        if (c + 3 < nch) ISSUE8(c + 3);

        const uint32_t ba = s0 + (c & 3) * I8_STAGE_B;
        const uint32_t bb = ba + I8_TILE_B;
#pragma unroll
        for (int k32 = 0; k32 < 2; k32++) {
            uint32_t a[2][4], b[8][2];
            {
                int arow = wm + (lane & 15);
                int au = k32 * 2 + (lane >> 4);
                ldsm_x4(a[0][0], a[0][1], a[0][2], a[0][3], ba + arow * 80 + au * 16);
                ldsm_x4(a[1][0], a[1][1], a[1][2], a[1][3], ba + (arow + 16) * 80 + au * 16);
            }
#pragma unroll
            for (int np = 0; np < 4; np++) {
                int brow = wn + np * 16 + (lane & 7) + ((lane >> 4) << 3);
                int bu = k32 * 2 + ((lane >> 3) & 1);
                uint32_t r0, r1, r2, r3;
                ldsm_x4(r0, r1, r2, r3, bb + brow * 80 + bu * 16);
                b[2 * np][0] = r0; b[2 * np][1] = r1;
                b[2 * np + 1][0] = r2; b[2 * np + 1][1] = r3;
            }
#pragma unroll
            for (int mt = 0; mt < 2; mt++)
#pragma unroll
                for (int nt = 0; nt < 8; nt++)
                    mma16832s8(acc[mt][nt], a[mt], b[nt]);
        }
    }
#undef ISSUE8

    // epilogue: direct row-major store + smem-staged transposed store (exact ints)
    __syncthreads();
    float* stage = (float*)dsm;   // pitch 132 floats: 128*132*4 = 67584 <= 81920
    const int g = lane >> 2, tig = lane & 3;
#pragma unroll
    for (int mt = 0; mt < 2; mt++) {
#pragma unroll
        for (int half = 0; half < 2; half++) {
            int r_loc = wm + mt * 16 + g + half * 8;
#pragma unroll
            for (int nt = 0; nt < 8; nt++) {
                int c_loc = wn + nt * 8 + 2 * tig;
                float2 o;
                o.x = (float)acc[mt][nt][half * 2 + 0];
                o.y = (float)acc[mt][nt][half * 2 + 1];
                *(float2*)&C[(size_t)(m0 + r_loc) * ldc + n0 + c_loc] = o;
                stage[(c_loc) * 132 + r_loc]     = o.x;
                stage[(c_loc + 1) * 132 + r_loc] = o.y;
            }
        }
    }
    __syncthreads();
    for (int i = tid; i < 128 * 32; i += 256) {
        int cc = i >> 5, u = i & 31;
        float4 val = *(const float4*)&stage[cc * 132 + u * 4];
        *(float4*)&C[(size_t)(n0 + cc) * ldc + m0 + u * 4] = val;
    }
}

// ---------------- launcher ----------------
extern "C" void kernel_launch(void* const* d_in, const int* in_sizes, int n_in,
                              void* d_out, int out_size)
{
    const float* x      = (const float*)d_in[0];   // [B,T,N]
    const float* weight = (const float*)d_in[1];   // [T,T]
    const float* bias   = (const float*)d_in[2];   // [T]
    const float* gumbel = (const float*)d_in[3];   // [N*N, 2]
    float* out = (float*)d_out;                    // [B,T,N] = [4096][2048]

    __half *p_xa3, *p_xb3, *p_wt2, *p_y2, *p_w3, *p_xt3;
    signed char* p_nm8;
    float* p_common;
    cudaGetSymbolAddress((void**)&p_xa3,    g_xa3);
    cudaGetSymbolAddress((void**)&p_xb3,    g_xb3);
    cudaGetSymbolAddress((void**)&p_nm8,    g_nm8);
    cudaGetSymbolAddress((void**)&p_wt2,    g_WT2);
    cudaGetSymbolAddress((void**)&p_y2,     g_Y2);
    cudaGetSymbolAddress((void**)&p_w3,     g_w3);
    cudaGetSymbolAddress((void**)&p_xt3,    g_xT3);
    cudaGetSymbolAddress((void**)&p_common, g_common);

    cudaFuncSetAttribute(hmma_gemm<HEPI_OUT>, cudaFuncAttributeMaxDynamicSharedMemorySize, HSMEM_BYTES);
    cudaFuncSetAttribute(hmma_gemm<HEPI_Y2>,  cudaFuncAttributeMaxDynamicSharedMemorySize, HSMEM_BYTES);
    cudaFuncSetAttribute(hmma_sim,            cudaFuncAttributeMaxDynamicSharedMemorySize, HSMEM_BYTES);
    cudaFuncSetAttribute(i8gemm_common,       cudaFuncAttributeMaxDynamicSharedMemorySize, I8SMEM_BYTES);

    // persistent side stream + events for fork-join capture (host handles only)
    static cudaStream_t sB = nullptr;
    static cudaEvent_t evFork = nullptr, evJoin = nullptr;
    if (sB == nullptr) {
        cudaStreamCreateWithFlags(&sB, cudaStreamNonBlocking);
        cudaEventCreateWithFlags(&evFork, cudaEventDisableTiming);
        cudaEventCreateWithFlags(&evJoin, cudaEventDisableTiming);
    }

    // ---- fork: Y chain on sB (depends only on inputs) ----
    cudaEventRecord(evFork, 0);
    cudaStreamWaitEvent(sB, evFork, 0);
    {
        dim3 grid(TT / 32, TT / 32); dim3 blk(32, 32);
        k_w3<<<grid, blk, 0, sB>>>(weight);
    }
    {
        dim3 grid(NN / 32, TT / 32, BB); dim3 blk(32, 32);
        k_xt3<<<grid, blk, 0, sB>>>(x);
    }
    {
        dim3 grid(NN / 128, TT / 128, BB);
        hmma_gemm<HEPI_Y2><<<grid, 256, HSMEM_BYTES, sB>>>(
            p_w3, p_xt3, nullptr, K3, K3, K3, 0,
            (size_t)NN * K3, TT, nullptr);
    }
    cudaEventRecord(evJoin, sB);

    // ---- adjacency chain on default stream ----
    k_colmean<<<(TT * NN) / 256, 256>>>(x);
    k_colnorm<<<NN / 256, 256>>>();
    {
        dim3 grid(NN / 32, TT / 32); dim3 blk(32, 32);
        k_writenorm<<<grid, blk>>>();
    }

    // sim GEMM over lower-triangle blocks; epilogue emits adj (both dirs) + nmask
    {
        const int NTILES = (NN / 128) * (NN / 128 + 1) / 2;   // 136
        hmma_sim<<<NTILES, 256, HSMEM_BYTES>>>(p_xa3, p_xb3, gumbel);
    }

    // common = nm @ nm^T over lower-triangle blocks, mirrored exactly
    {
        const int NTILES = (NN / 128) * (NN / 128 + 1) / 2;   // 136
        i8gemm_common<<<NTILES, 256, I8SMEM_BYTES>>>(p_nm8, p_nm8, p_common, NN, NN, NN, NN);
    }

    // deg partials, dinv
    {
        dim3 grid(NN / 256, 16);
        k_degpart<<<grid, 256>>>();
    }
    k_dinv<<<NN / 256, 256>>>();

    // WT2 = [fp16(Wn^T), fp16(Wn^T/8)]
    {
        dim3 grid(NN / 32, NN / 32); dim3 blk(32, 32);
        k_wnT<<<grid, blk>>>();
    }

    // ---- join: out GEMM needs g_Y2 (sB) + g_WT2 (default) ----
    cudaStreamWaitEvent(0, evJoin, 0);

    // out = Y @ Wn + bias  (2-term fp16 K-concat, K=4096)
    {
        dim3 grid(NN / 128, (BB * TT) / 128);
        hmma_gemm<HEPI_OUT><<<grid, 256, HSMEM_BYTES>>>(
            p_y2, p_wt2, out, K2, K2, K2, NN, 0, 0, bias);
    }
}

// round 9
// speedup vs baseline: 1.6529x; 1.3217x over previous
#include <cuda_runtime.h>
#include <cuda_fp16.h>
#include <cstdint>
#include <cstddef>

#define NN 2048      // nodes
#define BB 16        // batch
#define TT 256       // time/feature dim
#define K3 (3*TT)    // 768  (sim / Y split K)

// ---------------- device scratch (no allocations allowed) ----------------
__device__ float g_xavg[TT * NN];                 // [t][n]
__device__ float g_invn[NN];
__device__ __half g_xa3[(size_t)NN * K3];         // [n][768] = [h, l, h]
__device__ __half g_xb3[(size_t)NN * K3];         // [n][768] = [h, h, l]
__device__ __half g_w3[(size_t)TT * K3];          // [o][768] = [wh, wl, wh]
__device__ __half g_xT3[(size_t)BB * NN * K3];    // [b][n][768] = [xh, xh, xl]
__device__ unsigned char g_adj8[(size_t)NN * NN]; // directed adjacency 0/1
__device__ signed char g_nm8[(size_t)NN * NN];    // nmask 0/1 (s8)
__device__ float g_common[(size_t)NN * NN];       // exact integer counts
__device__ __half g_WT[(size_t)NN * NN];          // [d][s] = fp16(Wn^T)
__device__ __half g_Y[(size_t)BB * TT * NN];      // [4096][2048] = fp16(Y)
__device__ float g_degpart[16 * NN];
__device__ float g_dinv[NN];

// ---------------- PTX helpers (sm_80-level features only) ----------------
__device__ __forceinline__ uint32_t smem_u32(const void* p) {
    uint32_t a;
    asm("{ .reg .u64 t; cvta.to.shared.u64 t, %1; cvt.u32.u64 %0, t; }"
        : "=r"(a) : "l"(p));
    return a;
}

#define CP16(dst, src) \
    asm volatile("cp.async.cg.shared.global [%0], [%1], 16;" :: "r"(dst), "l"(src))
#define CP_COMMIT() asm volatile("cp.async.commit_group;" ::: "memory")
#define CP_WAIT2()  asm volatile("cp.async.wait_group 2;" ::: "memory")

__device__ __forceinline__ void ldsm_x4(uint32_t& r0, uint32_t& r1, uint32_t& r2,
                                        uint32_t& r3, uint32_t addr) {
    asm volatile("ldmatrix.sync.aligned.m8n8.x4.shared.b16 {%0,%1,%2,%3}, [%4];"
                 : "=r"(r0), "=r"(r1), "=r"(r2), "=r"(r3) : "r"(addr));
}

__device__ __forceinline__ void mma16816(float* c, const uint32_t* a, const uint32_t* b) {
    asm volatile(
        "mma.sync.aligned.m16n8k16.row.col.f32.f16.f16.f32 "
        "{%0,%1,%2,%3}, {%4,%5,%6,%7}, {%8,%9}, {%0,%1,%2,%3};"
        : "+f"(c[0]), "+f"(c[1]), "+f"(c[2]), "+f"(c[3])
        : "r"(a[0]), "r"(a[1]), "r"(a[2]), "r"(a[3]), "r"(b[0]), "r"(b[1]));
}

__device__ __forceinline__ void mma16832s8(int* c, const uint32_t* a, const uint32_t* b) {
    asm volatile(
        "mma.sync.aligned.m16n8k32.row.col.s32.s8.s8.s32 "
        "{%0,%1,%2,%3}, {%4,%5,%6,%7}, {%8,%9}, {%0,%1,%2,%3};"
        : "+r"(c[0]), "+r"(c[1]), "+r"(c[2]), "+r"(c[3])
        : "r"(a[0]), "r"(a[1]), "r"(a[2]), "r"(a[3]), "r"(b[0]), "r"(b[1]));
}

// decode 1D lower-triangle index -> (bi >= bj)
__device__ __forceinline__ void tri_decode(int idx, int& bi, int& bj) {
    int b = (int)((sqrtf(8.0f * idx + 1.0f) - 1.0f) * 0.5f);
    while ((b + 1) * (b + 2) / 2 <= idx) b++;
    while (b * (b + 1) / 2 > idx) b--;
    bi = b;
    bj = idx - b * (b + 1) / 2;
}

// ---------------- small kernels ----------------
__global__ void k_colmean(const float* __restrict__ x) {
    int e4 = blockIdx.x * blockDim.x + threadIdx.x;   // over (T*N)/4
    if (e4 >= TT * NN / 4) return;
    const float4* x4 = (const float4*)x;
    float4 s = make_float4(0.f, 0.f, 0.f, 0.f);
#pragma unroll
    for (int b = 0; b < BB; b++) {
        float4 v = x4[(size_t)b * (TT * NN / 4) + e4];
        s.x += v.x; s.y += v.y; s.z += v.z; s.w += v.w;
    }
    const float inv = 1.0f / BB;
    s.x *= inv; s.y *= inv; s.z *= inv; s.w *= inv;
    ((float4*)g_xavg)[e4] = s;
}

__global__ void k_colnorm() {
    int n = blockIdx.x * blockDim.x + threadIdx.x;
    if (n >= NN) return;
    float s = 0.f;
#pragma unroll 4
    for (int t = 0; t < TT; t++) { float v = g_xavg[t * NN + n]; s = fmaf(v, v, s); }
    float nrm = sqrtf(s);
    g_invn[n] = 1.0f / fmaxf(nrm, 1e-12f);
}

__global__ void k_writenorm() {   // grid (NN/32, TT/32), block (32,32)
    __shared__ float tile[32][33];
    int n0 = blockIdx.x * 32, t0 = blockIdx.y * 32;
    int tx = threadIdx.x, ty = threadIdx.y;
    tile[ty][tx] = g_xavg[(t0 + ty) * NN + n0 + tx] * g_invn[n0 + tx];
    __syncthreads();
    int n = n0 + ty, t = t0 + tx;
    float v = tile[tx][ty];
    __half h = __float2half_rn(v);
    __half l = __float2half_rn(v - __half2float(h));
    size_t base = (size_t)n * K3;
    g_xa3[base + t] = h; g_xa3[base + TT + t] = l; g_xa3[base + 2 * TT + t] = h;
    g_xb3[base + t] = h; g_xb3[base + TT + t] = h; g_xb3[base + 2 * TT + t] = l;
}

// weight [t][o] -> w3 [o][768] = [wh, wl, wh]
__global__ void k_w3(const float* __restrict__ w) {  // grid (8,8), block (32,32)
    __shared__ float tile[32][33];
    int o0 = blockIdx.x * 32, t0 = blockIdx.y * 32;
    int tx = threadIdx.x, ty = threadIdx.y;
    tile[ty][tx] = w[(t0 + ty) * TT + o0 + tx];
    __syncthreads();
    int o = o0 + ty, t = t0 + tx;
    float v = tile[tx][ty];
    __half h = __float2half_rn(v);
    __half l = __float2half_rn(v - __half2float(h));
    size_t base = (size_t)o * K3;
    g_w3[base + t] = h; g_w3[base + TT + t] = l; g_w3[base + 2 * TT + t] = h;
}

// x [b][t][n] -> xT3 [b][n][768] = [xh, xh, xl]
__global__ void k_xt3(const float* __restrict__ x) { // grid (NN/32, TT/32, BB), block (32,32)
    __shared__ float tile[32][33];
    int n0 = blockIdx.x * 32, t0 = blockIdx.y * 32, z = blockIdx.z;
    int tx = threadIdx.x, ty = threadIdx.y;
    tile[ty][tx] = x[(size_t)z * TT * NN + (t0 + ty) * NN + n0 + tx];
    __syncthreads();
    int n = n0 + ty, t = t0 + tx;
    float v = tile[tx][ty];
    __half h = __float2half_rn(v);
    __half l = __float2half_rn(v - __half2float(h));
    size_t base = ((size_t)z * NN + n) * K3;
    g_xT3[base + t] = h; g_xT3[base + TT + t] = h; g_xT3[base + 2 * TT + t] = l;
}

// deg partials: D[d] partial over 128 source rows; M = adj*(c>1)*c^2
__global__ void k_degpart() {
    int d = blockIdx.x * blockDim.x + threadIdx.x;
    int chunk = blockIdx.y;
    float s = 0.f;
    int s0 = chunk * 128;
#pragma unroll 4
    for (int r = 0; r < 128; r++) {
        size_t e = (size_t)(s0 + r) * NN + d;
        float c = g_common[e];
        if (g_adj8[e] != 0 && c > 1.0f) s += c * c;
    }
    g_degpart[chunk * NN + d] = s;
}

// dinv[d] = rsqrt(D_d); max_common cancels in Wn = M / sqrt(D_s * D_d)
__global__ void k_dinv() {
    int d = blockIdx.x * blockDim.x + threadIdx.x;
    if (d >= NN) return;
    float s = 0.f;
#pragma unroll
    for (int c = 0; c < 16; c++) s += g_degpart[c * NN + d];
    g_dinv[d] = (s > 0.f) ? rsqrtf(s) : 0.f;
}

// WT[d][s] = fp16(Wn^T), Wn[s,d] = M * dinv[s] * dinv[d]
__global__ void k_wnT() {         // grid (64,64): x = s-tile, y = d-tile; block (32,32)
    __shared__ unsigned char tileA[32][33];
    int bs = blockIdx.x * 32, bd = blockIdx.y * 32;
    int tx = threadIdx.x, ty = threadIdx.y;
    tileA[ty][tx] = g_adj8[(size_t)(bs + ty) * NN + bd + tx];  // adj[s][d] tile
    __syncthreads();
    int d = bd + ty, s = bs + tx;
    float c = g_common[(size_t)d * NN + s];      // = common[s][d] (symmetric)
    float m = 0.f;
    if (tileA[tx][ty] != 0 && c > 1.0f) m = c * c;
    float wn = m * g_dinv[s] * g_dinv[d];
    g_WT[(size_t)d * NN + s] = __float2half_rn(wn);
}

// ---------------- HMMA fp16 GEMM: 128x128 tile, 8 warps of 32x64, 4-stage ----------------
enum { HEPI_OUT = 1, HEPI_Y = 2 };

#define TILE_B 10240                 // 128 rows * 80 B
#define STAGE_B (2 * TILE_B)
#define HSMEM_BYTES (4 * STAGE_B)    // 81920

template <int EPI>
__global__ void __launch_bounds__(256, 2)
hmma_gemm(const __half* __restrict__ A, const __half* __restrict__ B,
          float* __restrict__ C, int K, int lda, int ldb, int ldc,
          size_t strideB, int rowsPerZ,
          const float* __restrict__ bias)
{
    extern __shared__ char dsm[];
    const int tid = threadIdx.x, lane = tid & 31, wid = tid >> 5;
    const int wm = (wid & 3) * 32;
    const int wn = (wid >> 2) * 64;
    const int m0 = blockIdx.y * 128, n0 = blockIdx.x * 128;
    const int rowbase = rowsPerZ * blockIdx.z;

    B += strideB * blockIdx.z;
    const uint32_t s0 = smem_u32(dsm);

    float acc[2][8][4];
#pragma unroll
    for (int i = 0; i < 2; i++)
#pragma unroll
        for (int j = 0; j < 8; j++)
#pragma unroll
            for (int q = 0; q < 4; q++) acc[i][j][q] = 0.f;

    const int nch = K >> 5;
    const int lr = tid >> 2, lu = tid & 3;
    const __half* gA = A + (size_t)(m0 + lr) * lda + lu * 8;
    const __half* gB = B + (size_t)(n0 + lr) * ldb + lu * 8;
    const uint32_t sm_off = lr * 80 + lu * 16;

#define ISSUE(c) do {                                                      \
        int _buf = (c) & 3;                                                \
        uint32_t _da = s0 + _buf * STAGE_B + sm_off;                       \
        uint32_t _db = _da + TILE_B;                                       \
        const __half* _ga = gA + ((size_t)(c) << 5);                       \
        const __half* _gb = gB + ((size_t)(c) << 5);                       \
        CP16(_da, _ga); CP16(_db, _gb);                                    \
        CP16(_da + 64 * 80, _ga + (size_t)64 * lda);                       \
        CP16(_db + 64 * 80, _gb + (size_t)64 * ldb);                       \
        CP_COMMIT();                                                       \
    } while (0)

    ISSUE(0); ISSUE(1); ISSUE(2);

    for (int c = 0; c < nch; c++) {
        CP_WAIT2();
        __syncthreads();
        if (c + 3 < nch) ISSUE(c + 3);

        const uint32_t ba = s0 + (c & 3) * STAGE_B;
        const uint32_t bb = ba + TILE_B;
#pragma unroll
        for (int k16 = 0; k16 < 2; k16++) {
            uint32_t a[2][4], b[8][2];
            {
                int arow = wm + (lane & 15);
                int au = k16 * 2 + (lane >> 4);
                ldsm_x4(a[0][0], a[0][1], a[0][2], a[0][3], ba + arow * 80 + au * 16);
                ldsm_x4(a[1][0], a[1][1], a[1][2], a[1][3], ba + (arow + 16) * 80 + au * 16);
            }
#pragma unroll
            for (int np = 0; np < 4; np++) {
                int brow = wn + np * 16 + (lane & 7) + ((lane >> 4) << 3);
                int bu = k16 * 2 + ((lane >> 3) & 1);
                uint32_t r0, r1, r2, r3;
                ldsm_x4(r0, r1, r2, r3, bb + brow * 80 + bu * 16);
                b[2 * np][0] = r0; b[2 * np][1] = r1;
                b[2 * np + 1][0] = r2; b[2 * np + 1][1] = r3;
            }
#pragma unroll
            for (int mt = 0; mt < 2; mt++)
#pragma unroll
                for (int nt = 0; nt < 8; nt++)
                    mma16816(acc[mt][nt], a[mt], b[nt]);
        }
    }
#undef ISSUE

    const int g = lane >> 2, tig = lane & 3;
#pragma unroll
    for (int mt = 0; mt < 2; mt++) {
#pragma unroll
        for (int half = 0; half < 2; half++) {
            int row = m0 + wm + mt * 16 + g + half * 8;
            int grow = rowbase + row;
#pragma unroll
            for (int nt = 0; nt < 8; nt++) {
                int col = n0 + wn + nt * 8 + 2 * tig;
                float v0 = acc[mt][nt][half * 2 + 0];
                float v1 = acc[mt][nt][half * 2 + 1];
                if (EPI == HEPI_OUT) {
                    float bv = bias[row & (TT - 1)];
                    float2 o;
                    o.x = v0 + bv;
                    o.y = v1 + bv;
                    *(float2*)&C[(size_t)row * ldc + col] = o;
                } else {  // HEPI_Y: single fp16 segment
                    __half2 seg; seg.x = __float2half_rn(v0); seg.y = __float2half_rn(v1);
                    *(__half2*)&g_Y[(size_t)grow * NN + col] = seg;
                }
            }
        }
    }
}

// ---------------- symmetric sim GEMM: lower-tri grid, fused adj + nmask ----------------
__global__ void __launch_bounds__(256, 2)
hmma_sim(const __half* __restrict__ A, const __half* __restrict__ B,
         const float* __restrict__ gumbel)
{
    extern __shared__ char dsm[];
    const int tid = threadIdx.x, lane = tid & 31, wid = tid >> 5;
    const int wm = (wid & 3) * 32;
    const int wn = (wid >> 2) * 64;
    int bi, bj;
    tri_decode(blockIdx.x, bi, bj);
    const int m0 = bi * 128, n0 = bj * 128;
    const int K = K3, lda = K3, ldb = K3;

    const uint32_t s0 = smem_u32(dsm);

    float acc[2][8][4];
#pragma unroll
    for (int i = 0; i < 2; i++)
#pragma unroll
        for (int j = 0; j < 8; j++)
#pragma unroll
            for (int q = 0; q < 4; q++) acc[i][j][q] = 0.f;

    const int nch = K >> 5;
    const int lr = tid >> 2, lu = tid & 3;
    const __half* gA = A + (size_t)(m0 + lr) * lda + lu * 8;
    const __half* gB = B + (size_t)(n0 + lr) * ldb + lu * 8;
    const uint32_t sm_off = lr * 80 + lu * 16;

#define ISSUE(c) do {                                                      \
        int _buf = (c) & 3;                                                \
        uint32_t _da = s0 + _buf * STAGE_B + sm_off;                       \
        uint32_t _db = _da + TILE_B;                                       \
        const __half* _ga = gA + ((size_t)(c) << 5);                       \
        const __half* _gb = gB + ((size_t)(c) << 5);                       \
        CP16(_da, _ga); CP16(_db, _gb);                                    \
        CP16(_da + 64 * 80, _ga + (size_t)64 * lda);                       \
        CP16(_db + 64 * 80, _gb + (size_t)64 * ldb);                       \
        CP_COMMIT();                                                       \
    } while (0)

    ISSUE(0); ISSUE(1); ISSUE(2);

    for (int c = 0; c < nch; c++) {
        CP_WAIT2();
        __syncthreads();
        if (c + 3 < nch) ISSUE(c + 3);

        const uint32_t ba = s0 + (c & 3) * STAGE_B;
        const uint32_t bb = ba + TILE_B;
#pragma unroll
        for (int k16 = 0; k16 < 2; k16++) {
            uint32_t a[2][4], b[8][2];
            {
                int arow = wm + (lane & 15);
                int au = k16 * 2 + (lane >> 4);
                ldsm_x4(a[0][0], a[0][1], a[0][2], a[0][3], ba + arow * 80 + au * 16);
                ldsm_x4(a[1][0], a[1][1], a[1][2], a[1][3], ba + (arow + 16) * 80 + au * 16);
            }
#pragma unroll
            for (int np = 0; np < 4; np++) {
                int brow = wn + np * 16 + (lane & 7) + ((lane >> 4) << 3);
                int bu = k16 * 2 + ((lane >> 3) & 1);
                uint32_t r0, r1, r2, r3;
                ldsm_x4(r0, r1, r2, r3, bb + brow * 80 + bu * 16);
                b[2 * np][0] = r0; b[2 * np][1] = r1;
                b[2 * np + 1][0] = r2; b[2 * np + 1][1] = r3;
            }
#pragma unroll
            for (int mt = 0; mt < 2; mt++)
#pragma unroll
                for (int nt = 0; nt < 8; nt++)
                    mma16816(acc[mt][nt], a[mt], b[nt]);
        }
    }
#undef ISSUE

    // epilogue: adj both orientations + nmask, staged in smem for coalesced stores
    __syncthreads();
    unsigned char* adjS = (unsigned char*)dsm;
    unsigned char* adjT = (unsigned char*)dsm + 16384;
    signed char*   nmS  = (signed char*)(dsm + 32768);
    signed char*   nmT  = (signed char*)(dsm + 49152);
    const float2* g2 = (const float2*)gumbel;
    const int g = lane >> 2, tig = lane & 3;
#pragma unroll
    for (int mt = 0; mt < 2; mt++) {
#pragma unroll
        for (int half = 0; half < 2; half++) {
            int r_loc = wm + mt * 16 + g + half * 8;
            int row = m0 + r_loc;
#pragma unroll
            for (int nt = 0; nt < 8; nt++) {
#pragma unroll
                for (int e = 0; e < 2; e++) {
                    int c_loc = wn + nt * 8 + 2 * tig + e;
                    int col = n0 + c_loc;
                    float v = acc[mt][nt][half * 2 + e];
                    float s = (v + 1.0f) * 0.5f;
                    float2 grc = g2[(size_t)row * NN + col];
                    float2 gcr = g2[(size_t)col * NN + row];
                    unsigned char arc = (s + grc.x > (1.0f - s) + grc.y) ? 1 : 0;
                    unsigned char acr = (s + gcr.x > (1.0f - s) + gcr.y) ? 1 : 0;
                    signed char nm = (row == col) ? 1 : (signed char)((arc | acr) ? 1 : 0);
                    adjS[r_loc * 128 + c_loc] = arc;
                    adjT[c_loc * 128 + r_loc] = acr;
                    nmS[r_loc * 128 + c_loc] = nm;
                    nmT[c_loc * 128 + r_loc] = nm;
                }
            }
        }
    }
    __syncthreads();
    for (int i = tid; i < 1024; i += 256) {
        int r = i >> 3, u = i & 7;
        *(uint4*)&g_adj8[(size_t)(m0 + r) * NN + n0 + u * 16] = *(const uint4*)(adjS + r * 128 + u * 16);
        *(uint4*)&g_adj8[(size_t)(n0 + r) * NN + m0 + u * 16] = *(const uint4*)(adjT + r * 128 + u * 16);
        *(uint4*)&g_nm8 [(size_t)(m0 + r) * NN + n0 + u * 16] = *(const uint4*)(nmS  + r * 128 + u * 16);
        *(uint4*)&g_nm8 [(size_t)(n0 + r) * NN + m0 + u * 16] = *(const uint4*)(nmT  + r * 128 + u * 16);
    }
}

// ---------------- int8 MMA GEMM, symmetric: common = nm @ nm^T (exact) ----------------
#define I8_TILE_B 10240
#define I8_STAGE_B (2 * I8_TILE_B)
#define I8SMEM_BYTES (4 * I8_STAGE_B)    // 81920

__global__ void __launch_bounds__(256, 2)
i8gemm_common(const signed char* __restrict__ A, const signed char* __restrict__ B,
              float* __restrict__ C, int K, int lda, int ldb, int ldc)
{
    extern __shared__ char dsm[];
    const int tid = threadIdx.x, lane = tid & 31, wid = tid >> 5;
    const int wm = (wid & 3) * 32;
    const int wn = (wid >> 2) * 64;
    int bi, bj;
    tri_decode(blockIdx.x, bi, bj);
    const int m0 = bi * 128, n0 = bj * 128;

    const uint32_t s0 = smem_u32(dsm);

    int acc[2][8][4];
#pragma unroll
    for (int i = 0; i < 2; i++)
#pragma unroll
        for (int j = 0; j < 8; j++)
#pragma unroll
            for (int q = 0; q < 4; q++) acc[i][j][q] = 0;

    const int nch = K >> 6;
    const int lr = tid >> 2, lu = tid & 3;
    const signed char* gA = A + (size_t)(m0 + lr) * lda + lu * 16;
    const signed char* gB = B + (size_t)(n0 + lr) * ldb + lu * 16;
    const uint32_t sm_off = lr * 80 + lu * 16;

#define ISSUE8(c) do {                                                     \
        int _buf = (c) & 3;                                                \
        uint32_t _da = s0 + _buf * I8_STAGE_B + sm_off;                    \
        uint32_t _db = _da + I8_TILE_B;                                    \
        const signed char* _ga = gA + ((size_t)(c) << 6);                  \
        const signed char* _gb = gB + ((size_t)(c) << 6);                  \
        CP16(_da, _ga); CP16(_db, _gb);                                    \
        CP16(_da + 64 * 80, _ga + (size_t)64 * lda);                       \
        CP16(_db + 64 * 80, _gb + (size_t)64 * ldb);                       \
        CP_COMMIT();                                                       \
    } while (0)

    ISSUE8(0); ISSUE8(1); ISSUE8(2);

    for (int c = 0; c < nch; c++) {
        CP_WAIT2();
        __syncthreads();
        if (c + 3 < nch) ISSUE8(c + 3);

        const uint32_t ba = s0 + (c & 3) * I8_STAGE_B;
        const uint32_t bb = ba + I8_TILE_B;
#pragma unroll
        for (int k32 = 0; k32 < 2; k32++) {
            uint32_t a[2][4], b[8][2];
            {
                int arow = wm + (lane & 15);
                int au = k32 * 2 + (lane >> 4);
                ldsm_x4(a[0][0], a[0][1], a[0][2], a[0][3], ba + arow * 80 + au * 16);
                ldsm_x4(a[1][0], a[1][1], a[1][2], a[1][3], ba + (arow + 16) * 80 + au * 16);
            }
#pragma unroll
            for (int np = 0; np < 4; np++) {
                int brow = wn + np * 16 + (lane & 7) + ((lane >> 4) << 3);
                int bu = k32 * 2 + ((lane >> 3) & 1);
                uint32_t r0, r1, r2, r3;
                ldsm_x4(r0, r1, r2, r3, bb + brow * 80 + bu * 16);
                b[2 * np][0] = r0; b[2 * np][1] = r1;
                b[2 * np + 1][0] = r2; b[2 * np + 1][1] = r3;
            }
#pragma unroll
            for (int mt = 0; mt < 2; mt++)
#pragma unroll
                for (int nt = 0; nt < 8; nt++)
                    mma16832s8(acc[mt][nt], a[mt], b[nt]);
        }
    }
#undef ISSUE8

    // epilogue: direct row-major store + smem-staged transposed store (exact ints)
    __syncthreads();
    float* stage = (float*)dsm;   // pitch 132 floats: 128*132*4 = 67584 <= 81920
    const int g = lane >> 2, tig = lane & 3;
#pragma unroll
    for (int mt = 0; mt < 2; mt++) {
#pragma unroll
        for (int half = 0; half < 2; half++) {
            int r_loc = wm + mt * 16 + g + half * 8;
#pragma unroll
            for (int nt = 0; nt < 8; nt++) {
                int c_loc = wn + nt * 8 + 2 * tig;
                float2 o;
                o.x = (float)acc[mt][nt][half * 2 + 0];
                o.y = (float)acc[mt][nt][half * 2 + 1];
                *(float2*)&C[(size_t)(m0 + r_loc) * ldc + n0 + c_loc] = o;
                stage[(c_loc) * 132 + r_loc]     = o.x;
                stage[(c_loc + 1) * 132 + r_loc] = o.y;
            }
        }
    }
    __syncthreads();
    for (int i = tid; i < 128 * 32; i += 256) {
        int cc = i >> 5, u = i & 31;
        float4 val = *(const float4*)&stage[cc * 132 + u * 4];
        *(float4*)&C[(size_t)(n0 + cc) * ldc + m0 + u * 4] = val;
    }
}

// ---------------- launcher ----------------
extern "C" void kernel_launch(void* const* d_in, const int* in_sizes, int n_in,
                              void* d_out, int out_size)
{
    const float* x      = (const float*)d_in[0];   // [B,T,N]
    const float* weight = (const float*)d_in[1];   // [T,T]
    const float* bias   = (const float*)d_in[2];   // [T]
    const float* gumbel = (const float*)d_in[3];   // [N*N, 2]
    float* out = (float*)d_out;                    // [B,T,N] = [4096][2048]

    __half *p_xa3, *p_xb3, *p_wt, *p_y, *p_w3, *p_xt3;
    signed char* p_nm8;
    float* p_common;
    cudaGetSymbolAddress((void**)&p_xa3,    g_xa3);
    cudaGetSymbolAddress((void**)&p_xb3,    g_xb3);
    cudaGetSymbolAddress((void**)&p_nm8,    g_nm8);
    cudaGetSymbolAddress((void**)&p_wt,     g_WT);
    cudaGetSymbolAddress((void**)&p_y,      g_Y);
    cudaGetSymbolAddress((void**)&p_w3,     g_w3);
    cudaGetSymbolAddress((void**)&p_xt3,    g_xT3);
    cudaGetSymbolAddress((void**)&p_common, g_common);

    cudaFuncSetAttribute(hmma_gemm<HEPI_OUT>, cudaFuncAttributeMaxDynamicSharedMemorySize, HSMEM_BYTES);
    cudaFuncSetAttribute(hmma_gemm<HEPI_Y>,   cudaFuncAttributeMaxDynamicSharedMemorySize, HSMEM_BYTES);
    cudaFuncSetAttribute(hmma_sim,            cudaFuncAttributeMaxDynamicSharedMemorySize, HSMEM_BYTES);
    cudaFuncSetAttribute(i8gemm_common,       cudaFuncAttributeMaxDynamicSharedMemorySize, I8SMEM_BYTES);

    // persistent side stream + events for fork-join capture (host handles only)
    static cudaStream_t sB = nullptr;
    static cudaEvent_t evFork = nullptr, evJoin = nullptr;
    if (sB == nullptr) {
        cudaStreamCreateWithFlags(&sB, cudaStreamNonBlocking);
        cudaEventCreateWithFlags(&evFork, cudaEventDisableTiming);
        cudaEventCreateWithFlags(&evJoin, cudaEventDisableTiming);
    }

    // ---- fork: Y chain on sB (depends only on inputs) ----
    cudaEventRecord(evFork, 0);
    cudaStreamWaitEvent(sB, evFork, 0);
    {
        dim3 grid(TT / 32, TT / 32); dim3 blk(32, 32);
        k_w3<<<grid, blk, 0, sB>>>(weight);
    }
    {
        dim3 grid(NN / 32, TT / 32, BB); dim3 blk(32, 32);
        k_xt3<<<grid, blk, 0, sB>>>(x);
    }
    {
        dim3 grid(NN / 128, TT / 128, BB);
        hmma_gemm<HEPI_Y><<<grid, 256, HSMEM_BYTES, sB>>>(
            p_w3, p_xt3, nullptr, K3, K3, K3, 0,
            (size_t)NN * K3, TT, nullptr);
    }
    cudaEventRecord(evJoin, sB);

    // ---- adjacency chain on default stream ----
    k_colmean<<<(TT * NN / 4) / 256, 256>>>(x);
    k_colnorm<<<NN / 256, 256>>>();
    {
        dim3 grid(NN / 32, TT / 32); dim3 blk(32, 32);
        k_writenorm<<<grid, blk>>>();
    }

    // sim GEMM over lower-triangle blocks; epilogue emits adj (both dirs) + nmask
    {
        const int NTILES = (NN / 128) * (NN / 128 + 1) / 2;   // 136
        hmma_sim<<<NTILES, 256, HSMEM_BYTES>>>(p_xa3, p_xb3, gumbel);
    }

    // common = nm @ nm^T over lower-triangle blocks, mirrored exactly
    {
        const int NTILES = (NN / 128) * (NN / 128 + 1) / 2;   // 136
        i8gemm_common<<<NTILES, 256, I8SMEM_BYTES>>>(p_nm8, p_nm8, p_common, NN, NN, NN, NN);
    }

    // deg partials, dinv
    {
        dim3 grid(NN / 256, 16);
        k_degpart<<<grid, 256>>>();
    }
    k_dinv<<<NN / 256, 256>>>();

    // WT = fp16(Wn^T)
    {
        dim3 grid(NN / 32, NN / 32); dim3 blk(32, 32);
        k_wnT<<<grid, blk>>>();
    }

    // ---- join: out GEMM needs g_Y (sB) + g_WT (default) ----
    cudaStreamWaitEvent(0, evJoin, 0);

    // out = Y @ Wn + bias  (single-term fp16, K=2048)
    {
        dim3 grid(NN / 128, (BB * TT) / 128);
        hmma_gemm<HEPI_OUT><<<grid, 256, HSMEM_BYTES>>>(
            p_y, p_wt, out, NN, NN, NN, NN, 0, 0, bias);
    }
}

// round 10
// speedup vs baseline: 1.6785x; 1.0155x over previous
#include <cuda_runtime.h>
#include <cuda_fp16.h>
#include <cstdint>
#include <cstddef>

#define NN 2048      // nodes
#define BB 16        // batch
#define TT 256       // time/feature dim
#define K3 (3*TT)    // 768  (sim split K)

// ---------------- device scratch (no allocations allowed) ----------------
__device__ float g_xavg[TT * NN];                 // [t][n]
__device__ float g_invn[NN];
__device__ __half g_xa3[(size_t)NN * K3];         // [n][768] = [h, l, h]
__device__ __half g_xb3[(size_t)NN * K3];         // [n][768] = [h, h, l]
__device__ __half g_wT[TT * TT];                  // [o][t] fp16
__device__ __half g_xT[(size_t)BB * NN * TT];     // [b][n][t] fp16
__device__ unsigned char g_adj8[(size_t)NN * NN]; // directed adjacency 0/1
__device__ signed char g_nm8[(size_t)NN * NN];    // nmask 0/1 (s8)
__device__ float g_common[(size_t)NN * NN];       // exact integer counts
__device__ __half g_WT[(size_t)NN * NN];          // [d][s] = fp16(Wn^T)
__device__ __half g_Y[(size_t)BB * TT * NN];      // [4096][2048] fp16(Y)
__device__ unsigned long long g_deg64[NN];        // exact integer deg sums
__device__ float g_dinv[NN];

// ---------------- PTX helpers (sm_80-level features only) ----------------
__device__ __forceinline__ uint32_t smem_u32(const void* p) {
    uint32_t a;
    asm("{ .reg .u64 t; cvta.to.shared.u64 t, %1; cvt.u32.u64 %0, t; }"
        : "=r"(a) : "l"(p));
    return a;
}

#define CP16(dst, src) \
    asm volatile("cp.async.cg.shared.global [%0], [%1], 16;" :: "r"(dst), "l"(src))
#define CP_COMMIT() asm volatile("cp.async.commit_group;" ::: "memory")
#define CP_WAIT2()  asm volatile("cp.async.wait_group 2;" ::: "memory")

__device__ __forceinline__ void ldsm_x4(uint32_t& r0, uint32_t& r1, uint32_t& r2,
                                        uint32_t& r3, uint32_t addr) {
    asm volatile("ldmatrix.sync.aligned.m8n8.x4.shared.b16 {%0,%1,%2,%3}, [%4];"
                 : "=r"(r0), "=r"(r1), "=r"(r2), "=r"(r3) : "r"(addr));
}

__device__ __forceinline__ void mma16816(float* c, const uint32_t* a, const uint32_t* b) {
    asm volatile(
        "mma.sync.aligned.m16n8k16.row.col.f32.f16.f16.f32 "
        "{%0,%1,%2,%3}, {%4,%5,%6,%7}, {%8,%9}, {%0,%1,%2,%3};"
        : "+f"(c[0]), "+f"(c[1]), "+f"(c[2]), "+f"(c[3])
        : "r"(a[0]), "r"(a[1]), "r"(a[2]), "r"(a[3]), "r"(b[0]), "r"(b[1]));
}

__device__ __forceinline__ void mma16832s8(int* c, const uint32_t* a, const uint32_t* b) {
    asm volatile(
        "mma.sync.aligned.m16n8k32.row.col.s32.s8.s8.s32 "
        "{%0,%1,%2,%3}, {%4,%5,%6,%7}, {%8,%9}, {%0,%1,%2,%3};"
        : "+r"(c[0]), "+r"(c[1]), "+r"(c[2]), "+r"(c[3])
        : "r"(a[0]), "r"(a[1]), "r"(a[2]), "r"(a[3]), "r"(b[0]), "r"(b[1]));
}

// decode 1D lower-triangle index -> (bi >= bj)
__device__ __forceinline__ void tri_decode(int idx, int& bi, int& bj) {
    int b = (int)((sqrtf(8.0f * idx + 1.0f) - 1.0f) * 0.5f);
    while ((b + 1) * (b + 2) / 2 <= idx) b++;
    while (b * (b + 1) / 2 > idx) b--;
    bi = b;
    bj = idx - b * (b + 1) / 2;
}

// ---------------- small kernels ----------------
__global__ void k_zerodeg() {                     // grid 8, block 256
    g_deg64[blockIdx.x * 256 + threadIdx.x] = 0ull;
}

__global__ void k_colmean(const float* __restrict__ x) {
    int e4 = blockIdx.x * blockDim.x + threadIdx.x;   // over (T*N)/4
    if (e4 >= TT * NN / 4) return;
    const float4* x4 = (const float4*)x;
    float4 s = make_float4(0.f, 0.f, 0.f, 0.f);
#pragma unroll
    for (int b = 0; b < BB; b++) {
        float4 v = x4[(size_t)b * (TT * NN / 4) + e4];
        s.x += v.x; s.y += v.y; s.z += v.z; s.w += v.w;
    }
    const float inv = 1.0f / BB;
    s.x *= inv; s.y *= inv; s.z *= inv; s.w *= inv;
    ((float4*)g_xavg)[e4] = s;
}

__global__ void k_colnorm() {
    int n = blockIdx.x * blockDim.x + threadIdx.x;
    if (n >= NN) return;
    float s = 0.f;
#pragma unroll 4
    for (int t = 0; t < TT; t++) { float v = g_xavg[t * NN + n]; s = fmaf(v, v, s); }
    float nrm = sqrtf(s);
    g_invn[n] = 1.0f / fmaxf(nrm, 1e-12f);
}

__global__ void k_writenorm() {   // grid (NN/32, TT/32), block (32,32)
    __shared__ float tile[32][33];
    int n0 = blockIdx.x * 32, t0 = blockIdx.y * 32;
    int tx = threadIdx.x, ty = threadIdx.y;
    tile[ty][tx] = g_xavg[(t0 + ty) * NN + n0 + tx] * g_invn[n0 + tx];
    __syncthreads();
    int n = n0 + ty, t = t0 + tx;
    float v = tile[tx][ty];
    __half h = __float2half_rn(v);
    __half l = __float2half_rn(v - __half2float(h));
    size_t base = (size_t)n * K3;
    g_xa3[base + t] = h; g_xa3[base + TT + t] = l; g_xa3[base + 2 * TT + t] = h;
    g_xb3[base + t] = h; g_xb3[base + TT + t] = h; g_xb3[base + 2 * TT + t] = l;
}

// weight [t][o] -> wT [o][t] fp16
__global__ void k_wT(const float* __restrict__ w) {  // grid (8,8), block (32,32)
    __shared__ float tile[32][33];
    int o0 = blockIdx.x * 32, t0 = blockIdx.y * 32;
    int tx = threadIdx.x, ty = threadIdx.y;
    tile[ty][tx] = w[(t0 + ty) * TT + o0 + tx];
    __syncthreads();
    g_wT[(o0 + ty) * TT + t0 + tx] = __float2half_rn(tile[tx][ty]);
}

// x [b][t][n] -> xT [b][n][t] fp16
__global__ void k_xT(const float* __restrict__ x) { // grid (NN/32, TT/32, BB), block (32,32)
    __shared__ float tile[32][33];
    int n0 = blockIdx.x * 32, t0 = blockIdx.y * 32, z = blockIdx.z;
    int tx = threadIdx.x, ty = threadIdx.y;
    tile[ty][tx] = x[(size_t)z * TT * NN + (t0 + ty) * NN + n0 + tx];
    __syncthreads();
    g_xT[((size_t)z * NN + n0 + ty) * TT + t0 + tx] = __float2half_rn(tile[tx][ty]);
}

// dinv[d] = rsqrt(deg_d) from exact integer deg; max_common cancels in Wn
__global__ void k_dinv() {
    int d = blockIdx.x * blockDim.x + threadIdx.x;
    if (d >= NN) return;
    float s = (float)g_deg64[d];
    g_dinv[d] = (s > 0.f) ? rsqrtf(s) : 0.f;
}

// WT[d][s] = fp16(Wn^T), Wn[s,d] = M * dinv[s] * dinv[d]
__global__ void k_wnT() {         // grid (64,64): x = s-tile, y = d-tile; block (32,32)
    __shared__ unsigned char tileA[32][33];
    int bs = blockIdx.x * 32, bd = blockIdx.y * 32;
    int tx = threadIdx.x, ty = threadIdx.y;
    tileA[ty][tx] = g_adj8[(size_t)(bs + ty) * NN + bd + tx];  // adj[s][d] tile
    __syncthreads();
    int d = bd + ty, s = bs + tx;
    float c = g_common[(size_t)d * NN + s];      // = common[s][d] (symmetric)
    float m = 0.f;
    if (tileA[tx][ty] != 0 && c > 1.0f) m = c * c;
    float wn = m * g_dinv[s] * g_dinv[d];
    g_WT[(size_t)d * NN + s] = __float2half_rn(wn);
}

// ---------------- HMMA fp16 GEMM: 128x128 tile, 8 warps of 32x64, 4-stage ----------------
enum { HEPI_OUT = 1, HEPI_Y = 2 };

#define TILE_B 10240                 // 128 rows * 80 B
#define STAGE_B (2 * TILE_B)
#define HSMEM_BYTES (4 * STAGE_B)    // 81920

template <int EPI>
__global__ void __launch_bounds__(256, 2)
hmma_gemm(const __half* __restrict__ A, const __half* __restrict__ B,
          float* __restrict__ C, int K, int lda, int ldb, int ldc,
          size_t strideB, int rowsPerZ,
          const float* __restrict__ bias)
{
    extern __shared__ char dsm[];
    const int tid = threadIdx.x, lane = tid & 31, wid = tid >> 5;
    const int wm = (wid & 3) * 32;
    const int wn = (wid >> 2) * 64;
    const int m0 = blockIdx.y * 128, n0 = blockIdx.x * 128;
    const int rowbase = rowsPerZ * blockIdx.z;

    B += strideB * blockIdx.z;
    const uint32_t s0 = smem_u32(dsm);

    float acc[2][8][4];
#pragma unroll
    for (int i = 0; i < 2; i++)
#pragma unroll
        for (int j = 0; j < 8; j++)
#pragma unroll
            for (int q = 0; q < 4; q++) acc[i][j][q] = 0.f;

    const int nch = K >> 5;
    const int lr = tid >> 2, lu = tid & 3;
    const __half* gA = A + (size_t)(m0 + lr) * lda + lu * 8;
    const __half* gB = B + (size_t)(n0 + lr) * ldb + lu * 8;
    const uint32_t sm_off = lr * 80 + lu * 16;

#define ISSUE(c) do {                                                      \
        int _buf = (c) & 3;                                                \
        uint32_t _da = s0 + _buf * STAGE_B + sm_off;                       \
        uint32_t _db = _da + TILE_B;                                       \
        const __half* _ga = gA + ((size_t)(c) << 5);                       \
        const __half* _gb = gB + ((size_t)(c) << 5);                       \
        CP16(_da, _ga); CP16(_db, _gb);                                    \
        CP16(_da + 64 * 80, _ga + (size_t)64 * lda);                       \
        CP16(_db + 64 * 80, _gb + (size_t)64 * ldb);                       \
        CP_COMMIT();                                                       \
    } while (0)

    ISSUE(0); ISSUE(1); ISSUE(2);

    for (int c = 0; c < nch; c++) {
        CP_WAIT2();
        __syncthreads();
        if (c + 3 < nch) ISSUE(c + 3);

        const uint32_t ba = s0 + (c & 3) * STAGE_B;
        const uint32_t bb = ba + TILE_B;
#pragma unroll
        for (int k16 = 0; k16 < 2; k16++) {
            uint32_t a[2][4], b[8][2];
            {
                int arow = wm + (lane & 15);
                int au = k16 * 2 + (lane >> 4);
                ldsm_x4(a[0][0], a[0][1], a[0][2], a[0][3], ba + arow * 80 + au * 16);
                ldsm_x4(a[1][0], a[1][1], a[1][2], a[1][3], ba + (arow + 16) * 80 + au * 16);
            }
#pragma unroll
            for (int np = 0; np < 4; np++) {
                int brow = wn + np * 16 + (lane & 7) + ((lane >> 4) << 3);
                int bu = k16 * 2 + ((lane >> 3) & 1);
                uint32_t r0, r1, r2, r3;
                ldsm_x4(r0, r1, r2, r3, bb + brow * 80 + bu * 16);
                b[2 * np][0] = r0; b[2 * np][1] = r1;
                b[2 * np + 1][0] = r2; b[2 * np + 1][1] = r3;
            }
#pragma unroll
            for (int mt = 0; mt < 2; mt++)
#pragma unroll
                for (int nt = 0; nt < 8; nt++)
                    mma16816(acc[mt][nt], a[mt], b[nt]);
        }
    }
#undef ISSUE

    const int g = lane >> 2, tig = lane & 3;
#pragma unroll
    for (int mt = 0; mt < 2; mt++) {
#pragma unroll
        for (int half = 0; half < 2; half++) {
            int row = m0 + wm + mt * 16 + g + half * 8;
            int grow = rowbase + row;
#pragma unroll
            for (int nt = 0; nt < 8; nt++) {
                int col = n0 + wn + nt * 8 + 2 * tig;
                float v0 = acc[mt][nt][half * 2 + 0];
                float v1 = acc[mt][nt][half * 2 + 1];
                if (EPI == HEPI_OUT) {
                    float bv = bias[row & (TT - 1)];
                    float2 o;
                    o.x = v0 + bv;
                    o.y = v1 + bv;
                    *(float2*)&C[(size_t)row * ldc + col] = o;
                } else {  // HEPI_Y: single fp16 segment
                    __half2 seg; seg.x = __float2half_rn(v0); seg.y = __float2half_rn(v1);
                    *(__half2*)&g_Y[(size_t)grow * NN + col] = seg;
                }
            }
        }
    }
}

// ---------------- symmetric sim GEMM: lower-tri grid, fused adj + nmask ----------------
__global__ void __launch_bounds__(256, 2)
hmma_sim(const __half* __restrict__ A, const __half* __restrict__ B,
         const float* __restrict__ gumbel)
{
    extern __shared__ char dsm[];
    const int tid = threadIdx.x, lane = tid & 31, wid = tid >> 5;
    const int wm = (wid & 3) * 32;
    const int wn = (wid >> 2) * 64;
    int bi, bj;
    tri_decode(blockIdx.x, bi, bj);
    const int m0 = bi * 128, n0 = bj * 128;
    const int K = K3, lda = K3, ldb = K3;

    const uint32_t s0 = smem_u32(dsm);

    float acc[2][8][4];
#pragma unroll
    for (int i = 0; i < 2; i++)
#pragma unroll
        for (int j = 0; j < 8; j++)
#pragma unroll
            for (int q = 0; q < 4; q++) acc[i][j][q] = 0.f;

    const int nch = K >> 5;
    const int lr = tid >> 2, lu = tid & 3;
    const __half* gA = A + (size_t)(m0 + lr) * lda + lu * 8;
    const __half* gB = B + (size_t)(n0 + lr) * ldb + lu * 8;
    const uint32_t sm_off = lr * 80 + lu * 16;

#define ISSUE(c) do {                                                      \
        int _buf = (c) & 3;                                                \
        uint32_t _da = s0 + _buf * STAGE_B + sm_off;                       \
        uint32_t _db = _da + TILE_B;                                       \
        const __half* _ga = gA + ((size_t)(c) << 5);                       \
        const __half* _gb = gB + ((size_t)(c) << 5);                       \
        CP16(_da, _ga); CP16(_db, _gb);                                    \
        CP16(_da + 64 * 80, _ga + (size_t)64 * lda);                       \
        CP16(_db + 64 * 80, _gb + (size_t)64 * ldb);                       \
        CP_COMMIT();                                                       \
    } while (0)

    ISSUE(0); ISSUE(1); ISSUE(2);

    for (int c = 0; c < nch; c++) {
        CP_WAIT2();
        __syncthreads();
        if (c + 3 < nch) ISSUE(c + 3);

        const uint32_t ba = s0 + (c & 3) * STAGE_B;
        const uint32_t bb = ba + TILE_B;
#pragma unroll
        for (int k16 = 0; k16 < 2; k16++) {
            uint32_t a[2][4], b[8][2];
            {
                int arow = wm + (lane & 15);
                int au = k16 * 2 + (lane >> 4);
                ldsm_x4(a[0][0], a[0][1], a[0][2], a[0][3], ba + arow * 80 + au * 16);
                ldsm_x4(a[1][0], a[1][1], a[1][2], a[1][3], ba + (arow + 16) * 80 + au * 16);
            }
#pragma unroll
            for (int np = 0; np < 4; np++) {
                int brow = wn + np * 16 + (lane & 7) + ((lane >> 4) << 3);
                int bu = k16 * 2 + ((lane >> 3) & 1);
                uint32_t r0, r1, r2, r3;
                ldsm_x4(r0, r1, r2, r3, bb + brow * 80 + bu * 16);
                b[2 * np][0] = r0; b[2 * np][1] = r1;
                b[2 * np + 1][0] = r2; b[2 * np + 1][1] = r3;
            }
#pragma unroll
            for (int mt = 0; mt < 2; mt++)
#pragma unroll
                for (int nt = 0; nt < 8; nt++)
                    mma16816(acc[mt][nt], a[mt], b[nt]);
        }
    }
#undef ISSUE

    // ---- epilogue: stage fp32 sim tile, then coalesced decision passes ----
    __syncthreads();
    float* simS = (float*)dsm;                                    // pitch 129: 66048 B
    uint32_t* bitS = (uint32_t*)(dsm + 66048);                    // 512 u32
    uint32_t* bitT = (uint32_t*)(dsm + 66048 + 2048);             // 512 u32
    const int g = lane >> 2, tig = lane & 3;
#pragma unroll
    for (int mt = 0; mt < 2; mt++)
#pragma unroll
        for (int half = 0; half < 2; half++) {
            int r_loc = wm + mt * 16 + g + half * 8;
#pragma unroll
            for (int nt = 0; nt < 8; nt++) {
                int c_loc = wn + nt * 8 + 2 * tig;
                simS[r_loc * 129 + c_loc]     = acc[mt][nt][half * 2 + 0];
                simS[r_loc * 129 + c_loc + 1] = acc[mt][nt][half * 2 + 1];
            }
        }
    __syncthreads();

    const float2* g2 = (const float2*)gumbel;
    // pass 1: direct orientation (coalesced gumbel + adj8 writes)
    for (int idx = tid; idx < 16384; idx += 256) {
        int r = idx >> 7, c = idx & 127;
        float v = simS[r * 129 + c];
        float s = (v + 1.0f) * 0.5f;
        float2 gg = g2[(size_t)(m0 + r) * NN + (n0 + c)];
        bool arc = (s + gg.x > (1.0f - s) + gg.y);
        unsigned bits = __ballot_sync(0xffffffffu, arc);
        if (lane == 0) bitS[idx >> 5] = bits;
        g_adj8[(size_t)(m0 + r) * NN + n0 + c] = arc ? 1 : 0;
    }
    // pass 2: mirror orientation (coalesced over rr)
    for (int idx = tid; idx < 16384; idx += 256) {
        int cc = idx >> 7, rr = idx & 127;
        float v = simS[rr * 129 + cc];          // sim(m0+rr, n0+cc), symmetric
        float s = (v + 1.0f) * 0.5f;
        float2 gg = g2[(size_t)(n0 + cc) * NN + (m0 + rr)];
        bool acr = (s + gg.x > (1.0f - s) + gg.y);
        unsigned bits = __ballot_sync(0xffffffffu, acr);
        if (lane == 0) bitT[idx >> 5] = bits;
        g_adj8[(size_t)(n0 + cc) * NN + m0 + rr] = acr ? 1 : 0;
    }
    __syncthreads();
    // pass 3: nmask both orientations
    const bool diag = (m0 == n0);
    for (int idx = tid; idx < 16384; idx += 256) {
        int r = idx >> 7, c = idx & 127;
        unsigned arc = (bitS[idx >> 5] >> (c & 31)) & 1u;
        unsigned acr = (bitT[c * 4 + (r >> 5)] >> (r & 31)) & 1u;
        signed char nm = (diag && r == c) ? 1 : (signed char)(arc | acr);
        g_nm8[(size_t)(m0 + r) * NN + n0 + c] = nm;
    }
    if (!diag) {
        for (int idx = tid; idx < 16384; idx += 256) {
            int cc = idx >> 7, rr = idx & 127;
            unsigned acr = (bitT[idx >> 5] >> (rr & 31)) & 1u;
            unsigned arc = (bitS[rr * 4 + (cc >> 5)] >> (cc & 31)) & 1u;
            g_nm8[(size_t)(n0 + cc) * NN + m0 + rr] = (signed char)(arc | acr);
        }
    }
}

// ---------------- int8 MMA GEMM, symmetric: common = nm @ nm^T (exact) + deg ----------------
#define I8_TILE_B 10240
#define I8_STAGE_B (2 * I8_TILE_B)
#define I8SMEM_BYTES (4 * I8_STAGE_B)    // 81920

__global__ void __launch_bounds__(256, 2)
i8gemm_common(const signed char* __restrict__ A, const signed char* __restrict__ B,
              float* __restrict__ C, int K, int lda, int ldb, int ldc)
{
    extern __shared__ char dsm[];
    const int tid = threadIdx.x, lane = tid & 31, wid = tid >> 5;
    const int wm = (wid & 3) * 32;
    const int wn = (wid >> 2) * 64;
    int bi, bj;
    tri_decode(blockIdx.x, bi, bj);
    const int m0 = bi * 128, n0 = bj * 128;

    const uint32_t s0 = smem_u32(dsm);

    int acc[2][8][4];
#pragma unroll
    for (int i = 0; i < 2; i++)
#pragma unroll
        for (int j = 0; j < 8; j++)
#pragma unroll
            for (int q = 0; q < 4; q++) acc[i][j][q] = 0;

    const int nch = K >> 6;
    const int lr = tid >> 2, lu = tid & 3;
    const signed char* gA = A + (size_t)(m0 + lr) * lda + lu * 16;
    const signed char* gB = B + (size_t)(n0 + lr) * ldb + lu * 16;
    const uint32_t sm_off = lr * 80 + lu * 16;

#define ISSUE8(c) do {                                                     \
        int _buf = (c) & 3;                                                \
        uint32_t _da = s0 + _buf * I8_STAGE_B + sm_off;                    \
        uint32_t _db = _da + I8_TILE_B;                                    \
        const signed char* _ga = gA + ((size_t)(c) << 6);                  \
        const signed char* _gb = gB + ((size_t)(c) << 6);                  \
        CP16(_da, _ga); CP16(_db, _gb);                                    \
        CP16(_da + 64 * 80, _ga + (size_t)64 * lda);                       \
        CP16(_db + 64 * 80, _gb + (size_t)64 * ldb);                       \
        CP_COMMIT();                                                       \
    } while (0)

    ISSUE8(0); ISSUE8(1); ISSUE8(2);

    for (int c = 0; c < nch; c++) {
        CP_WAIT2();
        __syncthreads();
        if (c + 3 < nch) ISSUE8(c + 3);

        const uint32_t ba = s0 + (c & 3) * I8_STAGE_B;
        const uint32_t bb = ba + I8_TILE_B;
#pragma unroll
        for (int k32 = 0; k32 < 2; k32++) {
            uint32_t a[2][4], b[8][2];
            {
                int arow = wm + (lane & 15);
                int au = k32 * 2 + (lane >> 4);
                ldsm_x4(a[0][0], a[0][1], a[0][2], a[0][3], ba + arow * 80 + au * 16);
                ldsm_x4(a[1][0], a[1][1], a[1][2], a[1][3], ba + (arow + 16) * 80 + au * 16);
            }
#pragma unroll
            for (int np = 0; np < 4; np++) {
                int brow = wn + np * 16 + (lane & 7) + ((lane >> 4) << 3);
                int bu = k32 * 2 + ((lane >> 3) & 1);
                uint32_t r0, r1, r2, r3;
                ldsm_x4(r0, r1, r2, r3, bb + brow * 80 + bu * 16);
                b[2 * np][0] = r0; b[2 * np][1] = r1;
                b[2 * np + 1][0] = r2; b[2 * np + 1][1] = r3;
            }
#pragma unroll
            for (int mt = 0; mt < 2; mt++)
#pragma unroll
                for (int nt = 0; nt < 8; nt++)
                    mma16832s8(acc[mt][nt], a[mt], b[nt]);
        }
    }
#undef ISSUE8

    const int g = lane >> 2, tig = lane & 3;
    const bool offd = (m0 != n0);

    // ---- phase 1: adj tiles into smem + zero deg partials ----
    __syncthreads();
    unsigned char* adjS = (unsigned char*)dsm;            // 16384
    unsigned char* adjT = (unsigned char*)dsm + 16384;    // 16384
    unsigned* degC = (unsigned*)(dsm + 32768);            // 512 B
    unsigned* degR = (unsigned*)(dsm + 33280);            // 512 B
    for (int i = tid; i < 1024; i += 256) {
        int r = i >> 3, u = i & 7;
        *(uint4*)(adjS + r * 128 + u * 16) = *(const uint4*)&g_adj8[(size_t)(m0 + r) * NN + n0 + u * 16];
        *(uint4*)(adjT + r * 128 + u * 16) = *(const uint4*)&g_adj8[(size_t)(n0 + r) * NN + m0 + u * 16];
    }
    if (tid < 128) { degC[tid] = 0; degR[tid] = 0; }
    __syncthreads();

    // ---- phase 2: direct common stores + deg partials ----
#pragma unroll
    for (int mt = 0; mt < 2; mt++) {
#pragma unroll
        for (int half = 0; half < 2; half++) {
            int r_loc = wm + mt * 16 + g + half * 8;
            unsigned rowsum = 0;
#pragma unroll
            for (int nt = 0; nt < 8; nt++) {
                int c_loc = wn + nt * 8 + 2 * tig;
                int v0 = acc[mt][nt][half * 2 + 0];
                int v1 = acc[mt][nt][half * 2 + 1];
                float2 o; o.x = (float)v0; o.y = (float)v1;
                *(float2*)&C[(size_t)(m0 + r_loc) * ldc + n0 + c_loc] = o;
                unsigned s0v = (v0 > 1 && adjS[r_loc * 128 + c_loc])     ? (unsigned)(v0 * v0) : 0u;
                unsigned s1v = (v1 > 1 && adjS[r_loc * 128 + c_loc + 1]) ? (unsigned)(v1 * v1) : 0u;
                // reduce over g (lanes stride 4)
                s0v += __shfl_down_sync(0xffffffffu, s0v, 16);
                s0v += __shfl_down_sync(0xffffffffu, s0v, 8);
                s0v += __shfl_down_sync(0xffffffffu, s0v, 4);
                s1v += __shfl_down_sync(0xffffffffu, s1v, 16);
                s1v += __shfl_down_sync(0xffffffffu, s1v, 8);
                s1v += __shfl_down_sync(0xffffffffu, s1v, 4);
                if (g == 0) {
                    atomicAdd(&degC[c_loc], s0v);
                    atomicAdd(&degC[c_loc + 1], s1v);
                }
                if (offd) {
                    unsigned t0 = (v0 > 1 && adjT[(c_loc) * 128 + r_loc])     ? (unsigned)(v0 * v0) : 0u;
                    unsigned t1 = (v1 > 1 && adjT[(c_loc + 1) * 128 + r_loc]) ? (unsigned)(v1 * v1) : 0u;
                    rowsum += t0 + t1;
                }
            }
            if (offd) {
                rowsum += __shfl_down_sync(0xffffffffu, rowsum, 2);
                rowsum += __shfl_down_sync(0xffffffffu, rowsum, 1);
                if (tig == 0) atomicAdd(&degR[r_loc], rowsum);
            }
        }
    }
    __syncthreads();

    // ---- phase 3: flush deg partials (exact integer, deterministic) ----
    if (tid < 128) {
        atomicAdd(&g_deg64[n0 + tid], (unsigned long long)degC[tid]);
        if (offd) atomicAdd(&g_deg64[m0 + tid], (unsigned long long)degR[tid]);
    }
    __syncthreads();

    // ---- phase 4+5: staged transpose for mirror common stores ----
    float* stage = (float*)dsm;   // pitch 132: 128*132*4 = 67584 <= 81920
#pragma unroll
    for (int mt = 0; mt < 2; mt++) {
#pragma unroll
        for (int half = 0; half < 2; half++) {
            int r_loc = wm + mt * 16 + g + half * 8;
#pragma unroll
            for (int nt = 0; nt < 8; nt++) {
                int c_loc = wn + nt * 8 + 2 * tig;
                stage[(c_loc) * 132 + r_loc]     = (float)acc[mt][nt][half * 2 + 0];
                stage[(c_loc + 1) * 132 + r_loc] = (float)acc[mt][nt][half * 2 + 1];
            }
        }
    }
    __syncthreads();
    for (int i = tid; i < 128 * 32; i += 256) {
        int cc = i >> 5, u = i & 31;
        float4 val = *(const float4*)&stage[cc * 132 + u * 4];
        *(float4*)&C[(size_t)(n0 + cc) * ldc + m0 + u * 4] = val;
    }
}

// ---------------- launcher ----------------
extern "C" void kernel_launch(void* const* d_in, const int* in_sizes, int n_in,
                              void* d_out, int out_size)
{
    const float* x      = (const float*)d_in[0];   // [B,T,N]
    const float* weight = (const float*)d_in[1];   // [T,T]
    const float* bias   = (const float*)d_in[2];   // [T]
    const float* gumbel = (const float*)d_in[3];   // [N*N, 2]
    float* out = (float*)d_out;                    // [B,T,N] = [4096][2048]

    __half *p_xa3, *p_xb3, *p_wt, *p_y, *p_wT, *p_xT;
    signed char* p_nm8;
    float* p_common;
    cudaGetSymbolAddress((void**)&p_xa3,    g_xa3);
    cudaGetSymbolAddress((void**)&p_xb3,    g_xb3);
    cudaGetSymbolAddress((void**)&p_nm8,    g_nm8);
    cudaGetSymbolAddress((void**)&p_wt,     g_WT);
    cudaGetSymbolAddress((void**)&p_y,      g_Y);
    cudaGetSymbolAddress((void**)&p_wT,     g_wT);
    cudaGetSymbolAddress((void**)&p_xT,     g_xT);
    cudaGetSymbolAddress((void**)&p_common, g_common);

    cudaFuncSetAttribute(hmma_gemm<HEPI_OUT>, cudaFuncAttributeMaxDynamicSharedMemorySize, HSMEM_BYTES);
    cudaFuncSetAttribute(hmma_gemm<HEPI_Y>,   cudaFuncAttributeMaxDynamicSharedMemorySize, HSMEM_BYTES);
    cudaFuncSetAttribute(hmma_sim,            cudaFuncAttributeMaxDynamicSharedMemorySize, HSMEM_BYTES);
    cudaFuncSetAttribute(i8gemm_common,       cudaFuncAttributeMaxDynamicSharedMemorySize, I8SMEM_BYTES);

    // persistent side stream + events for fork-join capture (host handles only)
    static cudaStream_t sB = nullptr;
    static cudaEvent_t evFork = nullptr, evJoin = nullptr;
    if (sB == nullptr) {
        cudaStreamCreateWithFlags(&sB, cudaStreamNonBlocking);
        cudaEventCreateWithFlags(&evFork, cudaEventDisableTiming);
        cudaEventCreateWithFlags(&evJoin, cudaEventDisableTiming);
    }

    // ---- fork: Y chain on sB (depends only on inputs) ----
    cudaEventRecord(evFork, 0);
    cudaStreamWaitEvent(sB, evFork, 0);
    {
        dim3 grid(TT / 32, TT / 32); dim3 blk(32, 32);
        k_wT<<<grid, blk, 0, sB>>>(weight);
    }
    {
        dim3 grid(NN / 32, TT / 32, BB); dim3 blk(32, 32);
        k_xT<<<grid, blk, 0, sB>>>(x);
    }
    {
        // Y[(b,o)][n] = sum_t wT[o][t] * xT[b][n][t]   (1-term fp16, K=256)
        dim3 grid(NN / 128, TT / 128, BB);
        hmma_gemm<HEPI_Y><<<grid, 256, HSMEM_BYTES, sB>>>(
            p_wT, p_xT, nullptr, TT, TT, TT, NN,
            (size_t)NN * TT, TT, nullptr);
    }
    cudaEventRecord(evJoin, sB);

    // ---- adjacency chain on default stream ----
    k_zerodeg<<<NN / 256, 256>>>();
    k_colmean<<<(TT * NN / 4) / 256, 256>>>(x);
    k_colnorm<<<NN / 256, 256>>>();
    {
        dim3 grid(NN / 32, TT / 32); dim3 blk(32, 32);
        k_writenorm<<<grid, blk>>>();
    }

    // sim GEMM over lower-triangle blocks; epilogue emits adj (both dirs) + nmask
    {
        const int NTILES = (NN / 128) * (NN / 128 + 1) / 2;   // 136
        hmma_sim<<<NTILES, 256, HSMEM_BYTES>>>(p_xa3, p_xb3, gumbel);
    }

    // common = nm @ nm^T over lower-triangle blocks + fused exact deg sums
    {
        const int NTILES = (NN / 128) * (NN / 128 + 1) / 2;   // 136
        i8gemm_common<<<NTILES, 256, I8SMEM_BYTES>>>(p_nm8, p_nm8, p_common, NN, NN, NN, NN);
    }

    k_dinv<<<NN / 256, 256>>>();

    // WT = fp16(Wn^T)
    {
        dim3 grid(NN / 32, NN / 32); dim3 blk(32, 32);
        k_wnT<<<grid, blk>>>();
    }

    // ---- join: out GEMM needs g_Y (sB) + g_WT (default) ----
    cudaStreamWaitEvent(0, evJoin, 0);

    // out = Y @ Wn + bias  (single-term fp16, K=2048)
    {
        dim3 grid(NN / 128, (BB * TT) / 128);
        hmma_gemm<HEPI_OUT><<<grid, 256, HSMEM_BYTES>>>(
            p_y, p_wt, out, NN, NN, NN, NN, 0, 0, bias);
    }
}

// round 11
// speedup vs baseline: 1.8844x; 1.1227x over previous
#include <cuda_runtime.h>
#include <cuda_fp16.h>
#include <cstdint>
#include <cstddef>

#define NN 2048      // nodes
#define BB 16        // batch
#define TT 256       // time/feature dim
#define K3 (3*TT)    // 768  (sim split K)

// ---------------- device scratch (no allocations allowed) ----------------
__device__ float g_xavg[TT * NN];                  // [t][n]
__device__ float g_invn[NN];
__device__ __half g_xa3[(size_t)NN * K3];          // [n][768] = [h, l, h]
__device__ __half g_xb3[(size_t)NN * K3];          // [n][768] = [h, h, l]
__device__ __half g_wT[TT * TT];                   // [o][t] fp16
__device__ __half g_xT[(size_t)BB * NN * TT];      // [b][n][t] fp16
__device__ unsigned char g_adj8[(size_t)NN * NN];  // directed adjacency 0/1
__device__ signed char g_nm8[(size_t)NN * NN];     // nmask 0/1 (s8)
__device__ unsigned short g_common16[(size_t)NN * NN]; // exact counts, lower-tri valid
__device__ __half g_WT[(size_t)NN * NN];           // [d][s] = fp16(Wn^T)
__device__ __half g_Y[(size_t)BB * TT * NN];       // [4096][2048] fp16(Y)
__device__ unsigned long long g_deg64[NN];         // exact integer deg sums

// ---------------- PTX helpers (sm_80-level features only) ----------------
__device__ __forceinline__ uint32_t smem_u32(const void* p) {
    uint32_t a;
    asm("{ .reg .u64 t; cvta.to.shared.u64 t, %1; cvt.u32.u64 %0, t; }"
        : "=r"(a) : "l"(p));
    return a;
}

#define CP16(dst, src) \
    asm volatile("cp.async.cg.shared.global [%0], [%1], 16;" :: "r"(dst), "l"(src))
#define CP_COMMIT() asm volatile("cp.async.commit_group;" ::: "memory")
#define CP_WAIT2()  asm volatile("cp.async.wait_group 2;" ::: "memory")

__device__ __forceinline__ void ldsm_x4(uint32_t& r0, uint32_t& r1, uint32_t& r2,
                                        uint32_t& r3, uint32_t addr) {
    asm volatile("ldmatrix.sync.aligned.m8n8.x4.shared.b16 {%0,%1,%2,%3}, [%4];"
                 : "=r"(r0), "=r"(r1), "=r"(r2), "=r"(r3) : "r"(addr));
}

__device__ __forceinline__ void mma16816(float* c, const uint32_t* a, const uint32_t* b) {
    asm volatile(
        "mma.sync.aligned.m16n8k16.row.col.f32.f16.f16.f32 "
        "{%0,%1,%2,%3}, {%4,%5,%6,%7}, {%8,%9}, {%0,%1,%2,%3};"
        : "+f"(c[0]), "+f"(c[1]), "+f"(c[2]), "+f"(c[3])
        : "r"(a[0]), "r"(a[1]), "r"(a[2]), "r"(a[3]), "r"(b[0]), "r"(b[1]));
}

__device__ __forceinline__ void mma16832s8(int* c, const uint32_t* a, const uint32_t* b) {
    asm volatile(
        "mma.sync.aligned.m16n8k32.row.col.s32.s8.s8.s32 "
        "{%0,%1,%2,%3}, {%4,%5,%6,%7}, {%8,%9}, {%0,%1,%2,%3};"
        : "+r"(c[0]), "+r"(c[1]), "+r"(c[2]), "+r"(c[3])
        : "r"(a[0]), "r"(a[1]), "r"(a[2]), "r"(a[3]), "r"(b[0]), "r"(b[1]));
}

// decode 1D lower-triangle index -> (bi >= bj)
__device__ __forceinline__ void tri_decode(int idx, int& bi, int& bj) {
    int b = (int)((sqrtf(8.0f * idx + 1.0f) - 1.0f) * 0.5f);
    while ((b + 1) * (b + 2) / 2 <= idx) b++;
    while (b * (b + 1) / 2 > idx) b--;
    bi = b;
    bj = idx - b * (b + 1) / 2;
}

// ---------------- small kernels ----------------
// fused: batch-mean (xavg) + fp16 transpose xT; reads x exactly once
__global__ void k_xprep(const float* __restrict__ x) { // grid (NN/32, TT/32), block (32,32)
    __shared__ float tile[32][33];
    int n0 = blockIdx.x * 32, t0 = blockIdx.y * 32;
    int tx = threadIdx.x, ty = threadIdx.y;
    float acc = 0.f;
#pragma unroll
    for (int b = 0; b < BB; b++) {
        float v = x[(size_t)b * TT * NN + (t0 + ty) * NN + n0 + tx];
        acc += v;
        tile[ty][tx] = v;
        __syncthreads();
        g_xT[((size_t)b * NN + n0 + ty) * TT + t0 + tx] = __float2half_rn(tile[tx][ty]);
        __syncthreads();
    }
    g_xavg[(t0 + ty) * NN + n0 + tx] = acc * (1.0f / BB);
}

__global__ void k_colnorm() {     // also zeroes deg accumulators
    int n = blockIdx.x * blockDim.x + threadIdx.x;
    if (n >= NN) return;
    g_deg64[n] = 0ull;
    float s = 0.f;
#pragma unroll 4
    for (int t = 0; t < TT; t++) { float v = g_xavg[t * NN + n]; s = fmaf(v, v, s); }
    float nrm = sqrtf(s);
    g_invn[n] = 1.0f / fmaxf(nrm, 1e-12f);
}

__global__ void k_writenorm() {   // grid (NN/32, TT/32), block (32,32)
    __shared__ float tile[32][33];
    int n0 = blockIdx.x * 32, t0 = blockIdx.y * 32;
    int tx = threadIdx.x, ty = threadIdx.y;
    tile[ty][tx] = g_xavg[(t0 + ty) * NN + n0 + tx] * g_invn[n0 + tx];
    __syncthreads();
    int n = n0 + ty, t = t0 + tx;
    float v = tile[tx][ty];
    __half h = __float2half_rn(v);
    __half l = __float2half_rn(v - __half2float(h));
    size_t base = (size_t)n * K3;
    g_xa3[base + t] = h; g_xa3[base + TT + t] = l; g_xa3[base + 2 * TT + t] = h;
    g_xb3[base + t] = h; g_xb3[base + TT + t] = h; g_xb3[base + 2 * TT + t] = l;
}

// weight [t][o] -> wT [o][t] fp16
__global__ void k_wT(const float* __restrict__ w) {  // grid (8,8), block (32,32)
    __shared__ float tile[32][33];
    int o0 = blockIdx.x * 32, t0 = blockIdx.y * 32;
    int tx = threadIdx.x, ty = threadIdx.y;
    tile[ty][tx] = w[(t0 + ty) * TT + o0 + tx];
    __syncthreads();
    g_wT[(o0 + ty) * TT + t0 + tx] = __float2half_rn(tile[tx][ty]);
}

// WT[d][s] = fp16(Wn^T) over triangular 32-tile grid; both orientations per tile
__global__ void k_wnT() {         // grid 2080 (tri over 64 32-tiles), block (32,32)
    __shared__ unsigned char adjA[32][33];   // adj[bi-row][bj-col]
    __shared__ unsigned char adjB[32][33];   // adj[bj-row][bi-col]
    __shared__ unsigned short cm[32][33];    // common[bi-row][bj-col] (lower-tri valid)
    __shared__ float dI[32], dJ[32];         // rsqrt(deg) for bi/bj ranges
    int bi, bj;
    tri_decode(blockIdx.x, bi, bj);
    int tx = threadIdx.x, ty = threadIdx.y;
    int i0 = bi * 32, j0 = bj * 32;
    adjA[ty][tx] = g_adj8[(size_t)(i0 + ty) * NN + j0 + tx];
    adjB[ty][tx] = g_adj8[(size_t)(j0 + ty) * NN + i0 + tx];
    cm[ty][tx]   = g_common16[(size_t)(i0 + ty) * NN + j0 + tx];
    if (ty == 0) {
        float s = (float)g_deg64[i0 + tx];
        dI[tx] = (s > 0.f) ? rsqrtf(s) : 0.f;
    } else if (ty == 1) {
        float s = (float)g_deg64[j0 + tx];
        dJ[tx] = (s > 0.f) ? rsqrtf(s) : 0.f;
    }
    __syncthreads();
    // orientation 1: s = i0+tx, d = j0+ty
    {
        float c = (float)cm[tx][ty];
        float m = (adjA[tx][ty] && c > 1.0f) ? c * c : 0.f;
        float wn = m * dI[tx] * dJ[ty];
        g_WT[(size_t)(j0 + ty) * NN + i0 + tx] = __float2half_rn(wn);
    }
    // orientation 2: s = j0+tx, d = i0+ty (skip on diagonal: identical values)
    if (bi != bj) {
        float c = (float)cm[ty][tx];
        float m = (adjB[tx][ty] && c > 1.0f) ? c * c : 0.f;
        float wn = m * dJ[tx] * dI[ty];
        g_WT[(size_t)(i0 + ty) * NN + j0 + tx] = __float2half_rn(wn);
    }
}

// ---------------- HMMA fp16 GEMM: 128x128 tile, 8 warps of 32x64, 4-stage ----------------
enum { HEPI_OUT = 1, HEPI_Y = 2 };

#define TILE_B 10240                 // 128 rows * 80 B
#define STAGE_B (2 * TILE_B)
#define HSMEM_BYTES (4 * STAGE_B)    // 81920

template <int EPI>
__global__ void __launch_bounds__(256, 2)
hmma_gemm(const __half* __restrict__ A, const __half* __restrict__ B,
          float* __restrict__ C, int K, int lda, int ldb, int ldc,
          size_t strideB, int rowsPerZ,
          const float* __restrict__ bias)
{
    extern __shared__ char dsm[];
    const int tid = threadIdx.x, lane = tid & 31, wid = tid >> 5;
    const int wm = (wid & 3) * 32;
    const int wn = (wid >> 2) * 64;
    const int m0 = blockIdx.y * 128, n0 = blockIdx.x * 128;
    const int rowbase = rowsPerZ * blockIdx.z;

    B += strideB * blockIdx.z;
    const uint32_t s0 = smem_u32(dsm);

    float acc[2][8][4];
#pragma unroll
    for (int i = 0; i < 2; i++)
#pragma unroll
        for (int j = 0; j < 8; j++)
#pragma unroll
            for (int q = 0; q < 4; q++) acc[i][j][q] = 0.f;

    const int nch = K >> 5;
    const int lr = tid >> 2, lu = tid & 3;
    const __half* gA = A + (size_t)(m0 + lr) * lda + lu * 8;
    const __half* gB = B + (size_t)(n0 + lr) * ldb + lu * 8;
    const uint32_t sm_off = lr * 80 + lu * 16;

#define ISSUE(c) do {                                                      \
        int _buf = (c) & 3;                                                \
        uint32_t _da = s0 + _buf * STAGE_B + sm_off;                       \
        uint32_t _db = _da + TILE_B;                                       \
        const __half* _ga = gA + ((size_t)(c) << 5);                       \
        const __half* _gb = gB + ((size_t)(c) << 5);                       \
        CP16(_da, _ga); CP16(_db, _gb);                                    \
        CP16(_da + 64 * 80, _ga + (size_t)64 * lda);                       \
        CP16(_db + 64 * 80, _gb + (size_t)64 * ldb);                       \
        CP_COMMIT();                                                       \
    } while (0)

    ISSUE(0); ISSUE(1); ISSUE(2);

    for (int c = 0; c < nch; c++) {
        CP_WAIT2();
        __syncthreads();
        if (c + 3 < nch) ISSUE(c + 3);

        const uint32_t ba = s0 + (c & 3) * STAGE_B;
        const uint32_t bb = ba + TILE_B;
#pragma unroll
        for (int k16 = 0; k16 < 2; k16++) {
            uint32_t a[2][4], b[8][2];
            {
                int arow = wm + (lane & 15);
                int au = k16 * 2 + (lane >> 4);
                ldsm_x4(a[0][0], a[0][1], a[0][2], a[0][3], ba + arow * 80 + au * 16);
                ldsm_x4(a[1][0], a[1][1], a[1][2], a[1][3], ba + (arow + 16) * 80 + au * 16);
            }
#pragma unroll
            for (int np = 0; np < 4; np++) {
                int brow = wn + np * 16 + (lane & 7) + ((lane >> 4) << 3);
                int bu = k16 * 2 + ((lane >> 3) & 1);
                uint32_t r0, r1, r2, r3;
                ldsm_x4(r0, r1, r2, r3, bb + brow * 80 + bu * 16);
                b[2 * np][0] = r0; b[2 * np][1] = r1;
                b[2 * np + 1][0] = r2; b[2 * np + 1][1] = r3;
            }
#pragma unroll
            for (int mt = 0; mt < 2; mt++)
#pragma unroll
                for (int nt = 0; nt < 8; nt++)
                    mma16816(acc[mt][nt], a[mt], b[nt]);
        }
    }
#undef ISSUE

    const int g = lane >> 2, tig = lane & 3;
#pragma unroll
    for (int mt = 0; mt < 2; mt++) {
#pragma unroll
        for (int half = 0; half < 2; half++) {
            int row = m0 + wm + mt * 16 + g + half * 8;
            int grow = rowbase + row;
#pragma unroll
            for (int nt = 0; nt < 8; nt++) {
                int col = n0 + wn + nt * 8 + 2 * tig;
                float v0 = acc[mt][nt][half * 2 + 0];
                float v1 = acc[mt][nt][half * 2 + 1];
                if (EPI == HEPI_OUT) {
                    float bv = bias[row & (TT - 1)];
                    float2 o;
                    o.x = v0 + bv;
                    o.y = v1 + bv;
                    *(float2*)&C[(size_t)row * ldc + col] = o;
                } else {  // HEPI_Y: single fp16 segment
                    __half2 seg; seg.x = __float2half_rn(v0); seg.y = __float2half_rn(v1);
                    *(__half2*)&g_Y[(size_t)grow * NN + col] = seg;
                }
            }
        }
    }
}

// ---------------- symmetric sim GEMM: lower-tri grid, fused adj + nmask ----------------
__global__ void __launch_bounds__(256, 2)
hmma_sim(const __half* __restrict__ A, const __half* __restrict__ B,
         const float* __restrict__ gumbel)
{
    extern __shared__ char dsm[];
    const int tid = threadIdx.x, lane = tid & 31, wid = tid >> 5;
    const int wm = (wid & 3) * 32;
    const int wn = (wid >> 2) * 64;
    int bi, bj;
    tri_decode(blockIdx.x, bi, bj);
    const int m0 = bi * 128, n0 = bj * 128;
    const int K = K3, lda = K3, ldb = K3;

    const uint32_t s0 = smem_u32(dsm);

    float acc[2][8][4];
#pragma unroll
    for (int i = 0; i < 2; i++)
#pragma unroll
        for (int j = 0; j < 8; j++)
#pragma unroll
            for (int q = 0; q < 4; q++) acc[i][j][q] = 0.f;

    const int nch = K >> 5;
    const int lr = tid >> 2, lu = tid & 3;
    const __half* gA = A + (size_t)(m0 + lr) * lda + lu * 8;
    const __half* gB = B + (size_t)(n0 + lr) * ldb + lu * 8;
    const uint32_t sm_off = lr * 80 + lu * 16;

#define ISSUE(c) do {                                                      \
        int _buf = (c) & 3;                                                \
        uint32_t _da = s0 + _buf * STAGE_B + sm_off;                       \
        uint32_t _db = _da + TILE_B;                                       \
        const __half* _ga = gA + ((size_t)(c) << 5);                       \
        const __half* _gb = gB + ((size_t)(c) << 5);                       \
        CP16(_da, _ga); CP16(_db, _gb);                                    \
        CP16(_da + 64 * 80, _ga + (size_t)64 * lda);                       \
        CP16(_db + 64 * 80, _gb + (size_t)64 * ldb);                       \
        CP_COMMIT();                                                       \
    } while (0)

    ISSUE(0); ISSUE(1); ISSUE(2);

    for (int c = 0; c < nch; c++) {
        CP_WAIT2();
        __syncthreads();
        if (c + 3 < nch) ISSUE(c + 3);

        const uint32_t ba = s0 + (c & 3) * STAGE_B;
        const uint32_t bb = ba + TILE_B;
#pragma unroll
        for (int k16 = 0; k16 < 2; k16++) {
            uint32_t a[2][4], b[8][2];
            {
                int arow = wm + (lane & 15);
                int au = k16 * 2 + (lane >> 4);
                ldsm_x4(a[0][0], a[0][1], a[0][2], a[0][3], ba + arow * 80 + au * 16);
                ldsm_x4(a[1][0], a[1][1], a[1][2], a[1][3], ba + (arow + 16) * 80 + au * 16);
            }
#pragma unroll
            for (int np = 0; np < 4; np++) {
                int brow = wn + np * 16 + (lane & 7) + ((lane >> 4) << 3);
                int bu = k16 * 2 + ((lane >> 3) & 1);
                uint32_t r0, r1, r2, r3;
                ldsm_x4(r0, r1, r2, r3, bb + brow * 80 + bu * 16);
                b[2 * np][0] = r0; b[2 * np][1] = r1;
                b[2 * np + 1][0] = r2; b[2 * np + 1][1] = r3;
            }
#pragma unroll
            for (int mt = 0; mt < 2; mt++)
#pragma unroll
                for (int nt = 0; nt < 8; nt++)
                    mma16816(acc[mt][nt], a[mt], b[nt]);
        }
    }
#undef ISSUE

    // ---- epilogue: stage fp32 sim tile, then coalesced decision passes ----
    __syncthreads();
    float* simS = (float*)dsm;                                    // pitch 129: 66048 B
    uint32_t* bitS = (uint32_t*)(dsm + 66048);                    // 512 u32
    uint32_t* bitT = (uint32_t*)(dsm + 66048 + 2048);             // 512 u32
    const int g = lane >> 2, tig = lane & 3;
#pragma unroll
    for (int mt = 0; mt < 2; mt++)
#pragma unroll
        for (int half = 0; half < 2; half++) {
            int r_loc = wm + mt * 16 + g + half * 8;
#pragma unroll
            for (int nt = 0; nt < 8; nt++) {
                int c_loc = wn + nt * 8 + 2 * tig;
                simS[r_loc * 129 + c_loc]     = acc[mt][nt][half * 2 + 0];
                simS[r_loc * 129 + c_loc + 1] = acc[mt][nt][half * 2 + 1];
            }
        }
    __syncthreads();

    const float2* g2 = (const float2*)gumbel;
    // pass 1: direct orientation (coalesced gumbel + adj8 writes)
    for (int idx = tid; idx < 16384; idx += 256) {
        int r = idx >> 7, c = idx & 127;
        float v = simS[r * 129 + c];
        float s = (v + 1.0f) * 0.5f;
        float2 gg = g2[(size_t)(m0 + r) * NN + (n0 + c)];
        bool arc = (s + gg.x > (1.0f - s) + gg.y);
        unsigned bits = __ballot_sync(0xffffffffu, arc);
        if (lane == 0) bitS[idx >> 5] = bits;
        g_adj8[(size_t)(m0 + r) * NN + n0 + c] = arc ? 1 : 0;
    }
    // pass 2: mirror orientation (coalesced over rr)
    for (int idx = tid; idx < 16384; idx += 256) {
        int cc = idx >> 7, rr = idx & 127;
        float v = simS[rr * 129 + cc];          // sim(m0+rr, n0+cc), symmetric
        float s = (v + 1.0f) * 0.5f;
        float2 gg = g2[(size_t)(n0 + cc) * NN + (m0 + rr)];
        bool acr = (s + gg.x > (1.0f - s) + gg.y);
        unsigned bits = __ballot_sync(0xffffffffu, acr);
        if (lane == 0) bitT[idx >> 5] = bits;
        g_adj8[(size_t)(n0 + cc) * NN + m0 + rr] = acr ? 1 : 0;
    }
    __syncthreads();
    // pass 3: nmask both orientations
    const bool diag = (m0 == n0);
    for (int idx = tid; idx < 16384; idx += 256) {
        int r = idx >> 7, c = idx & 127;
        unsigned arc = (bitS[idx >> 5] >> (c & 31)) & 1u;
        unsigned acr = (bitT[c * 4 + (r >> 5)] >> (r & 31)) & 1u;
        signed char nm = (diag && r == c) ? 1 : (signed char)(arc | acr);
        g_nm8[(size_t)(m0 + r) * NN + n0 + c] = nm;
    }
    if (!diag) {
        for (int idx = tid; idx < 16384; idx += 256) {
            int cc = idx >> 7, rr = idx & 127;
            unsigned acr = (bitT[idx >> 5] >> (rr & 31)) & 1u;
            unsigned arc = (bitS[rr * 4 + (cc >> 5)] >> (cc & 31)) & 1u;
            g_nm8[(size_t)(n0 + cc) * NN + m0 + rr] = (signed char)(arc | acr);
        }
    }
}

// ---------------- int8 MMA GEMM, symmetric: common = nm @ nm^T (exact, u16) + deg ----------------
#define I8_TILE_B 10240
#define I8_STAGE_B (2 * I8_TILE_B)
#define I8SMEM_BYTES (4 * I8_STAGE_B)    // 81920

__global__ void __launch_bounds__(256, 2)
i8gemm_common(const signed char* __restrict__ A, const signed char* __restrict__ B,
              unsigned short* __restrict__ C, int K, int lda, int ldb, int ldc)
{
    extern __shared__ char dsm[];
    const int tid = threadIdx.x, lane = tid & 31, wid = tid >> 5;
    const int wm = (wid & 3) * 32;
    const int wn = (wid >> 2) * 64;
    int bi, bj;
    tri_decode(blockIdx.x, bi, bj);
    const int m0 = bi * 128, n0 = bj * 128;

    const uint32_t s0 = smem_u32(dsm);

    int acc[2][8][4];
#pragma unroll
    for (int i = 0; i < 2; i++)
#pragma unroll
        for (int j = 0; j < 8; j++)
#pragma unroll
            for (int q = 0; q < 4; q++) acc[i][j][q] = 0;

    const int nch = K >> 6;
    const int lr = tid >> 2, lu = tid & 3;
    const signed char* gA = A + (size_t)(m0 + lr) * lda + lu * 16;
    const signed char* gB = B + (size_t)(n0 + lr) * ldb + lu * 16;
    const uint32_t sm_off = lr * 80 + lu * 16;

#define ISSUE8(c) do {                                                     \
        int _buf = (c) & 3;                                                \
        uint32_t _da = s0 + _buf * I8_STAGE_B + sm_off;                    \
        uint32_t _db = _da + I8_TILE_B;                                    \
        const signed char* _ga = gA + ((size_t)(c) << 6);                  \
        const signed char* _gb = gB + ((size_t)(c) << 6);                  \
        CP16(_da, _ga); CP16(_db, _gb);                                    \
        CP16(_da + 64 * 80, _ga + (size_t)64 * lda);                       \
        CP16(_db + 64 * 80, _gb + (size_t)64 * ldb);                       \
        CP_COMMIT();                                                       \
    } while (0)

    ISSUE8(0); ISSUE8(1); ISSUE8(2);

    for (int c = 0; c < nch; c++) {
        CP_WAIT2();
        __syncthreads();
        if (c + 3 < nch) ISSUE8(c + 3);

        const uint32_t ba = s0 + (c & 3) * I8_STAGE_B;
        const uint32_t bb = ba + I8_TILE_B;
#pragma unroll
        for (int k32 = 0; k32 < 2; k32++) {
            uint32_t a[2][4], b[8][2];
            {
                int arow = wm + (lane & 15);
                int au = k32 * 2 + (lane >> 4);
                ldsm_x4(a[0][0], a[0][1], a[0][2], a[0][3], ba + arow * 80 + au * 16);
                ldsm_x4(a[1][0], a[1][1], a[1][2], a[1][3], ba + (arow + 16) * 80 + au * 16);
            }
#pragma unroll
            for (int np = 0; np < 4; np++) {
                int brow = wn + np * 16 + (lane & 7) + ((lane >> 4) << 3);
                int bu = k32 * 2 + ((lane >> 3) & 1);
                uint32_t r0, r1, r2, r3;
                ldsm_x4(r0, r1, r2, r3, bb + brow * 80 + bu * 16);
                b[2 * np][0] = r0; b[2 * np][1] = r1;
                b[2 * np + 1][0] = r2; b[2 * np + 1][1] = r3;
            }
#pragma unroll
            for (int mt = 0; mt < 2; mt++)
#pragma unroll
                for (int nt = 0; nt < 8; nt++)
                    mma16832s8(acc[mt][nt], a[mt], b[nt]);
        }
    }
#undef ISSUE8

    const int g = lane >> 2, tig = lane & 3;
    const bool offd = (m0 != n0);

    // ---- phase 1: adj tiles into smem + zero deg partials ----
    __syncthreads();
    unsigned char* adjS = (unsigned char*)dsm;            // 16384
    unsigned char* adjT = (unsigned char*)dsm + 16384;    // 16384
    unsigned* degC = (unsigned*)(dsm + 32768);            // 512 B
    unsigned* degR = (unsigned*)(dsm + 33280);            // 512 B
    for (int i = tid; i < 1024; i += 256) {
        int r = i >> 3, u = i & 7;
        *(uint4*)(adjS + r * 128 + u * 16) = *(const uint4*)&g_adj8[(size_t)(m0 + r) * NN + n0 + u * 16];
        *(uint4*)(adjT + r * 128 + u * 16) = *(const uint4*)&g_adj8[(size_t)(n0 + r) * NN + m0 + u * 16];
    }
    if (tid < 128) { degC[tid] = 0; degR[tid] = 0; }
    __syncthreads();

    // ---- phase 2: lower-tri u16 common stores + deg partials ----
#pragma unroll
    for (int mt = 0; mt < 2; mt++) {
#pragma unroll
        for (int half = 0; half < 2; half++) {
            int r_loc = wm + mt * 16 + g + half * 8;
            unsigned rowsum = 0;
#pragma unroll
            for (int nt = 0; nt < 8; nt++) {
                int c_loc = wn + nt * 8 + 2 * tig;
                int v0 = acc[mt][nt][half * 2 + 0];
                int v1 = acc[mt][nt][half * 2 + 1];
                ushort2 o; o.x = (unsigned short)v0; o.y = (unsigned short)v1;
                *(ushort2*)&C[(size_t)(m0 + r_loc) * ldc + n0 + c_loc] = o;
                unsigned s0v = (v0 > 1 && adjS[r_loc * 128 + c_loc])     ? (unsigned)(v0 * v0) : 0u;
                unsigned s1v = (v1 > 1 && adjS[r_loc * 128 + c_loc + 1]) ? (unsigned)(v1 * v1) : 0u;
                s0v += __shfl_down_sync(0xffffffffu, s0v, 16);
                s0v += __shfl_down_sync(0xffffffffu, s0v, 8);
                s0v += __shfl_down_sync(0xffffffffu, s0v, 4);
                s1v += __shfl_down_sync(0xffffffffu, s1v, 16);
                s1v += __shfl_down_sync(0xffffffffu, s1v, 8);
                s1v += __shfl_down_sync(0xffffffffu, s1v, 4);
                if (g == 0) {
                    atomicAdd(&degC[c_loc], s0v);
                    atomicAdd(&degC[c_loc + 1], s1v);
                }
                if (offd) {
                    unsigned t0 = (v0 > 1 && adjT[(c_loc) * 128 + r_loc])     ? (unsigned)(v0 * v0) : 0u;
                    unsigned t1 = (v1 > 1 && adjT[(c_loc + 1) * 128 + r_loc]) ? (unsigned)(v1 * v1) : 0u;
                    rowsum += t0 + t1;
                }
            }
            if (offd) {
                rowsum += __shfl_down_sync(0xffffffffu, rowsum, 2);
                rowsum += __shfl_down_sync(0xffffffffu, rowsum, 1);
                if (tig == 0) atomicAdd(&degR[r_loc], rowsum);
            }
        }
    }
    __syncthreads();

    // ---- phase 3: flush deg partials (exact integer, deterministic) ----
    if (tid < 128) {
        atomicAdd(&g_deg64[n0 + tid], (unsigned long long)degC[tid]);
        if (offd) atomicAdd(&g_deg64[m0 + tid], (unsigned long long)degR[tid]);
    }
}

// ---------------- launcher ----------------
extern "C" void kernel_launch(void* const* d_in, const int* in_sizes, int n_in,
                              void* d_out, int out_size)
{
    const float* x      = (const float*)d_in[0];   // [B,T,N]
    const float* weight = (const float*)d_in[1];   // [T,T]
    const float* bias   = (const float*)d_in[2];   // [T]
    const float* gumbel = (const float*)d_in[3];   // [N*N, 2]
    float* out = (float*)d_out;                    // [B,T,N] = [4096][2048]

    __half *p_xa3, *p_xb3, *p_wt, *p_y, *p_wT, *p_xT;
    signed char* p_nm8;
    unsigned short* p_common16;
    cudaGetSymbolAddress((void**)&p_xa3,      g_xa3);
    cudaGetSymbolAddress((void**)&p_xb3,      g_xb3);
    cudaGetSymbolAddress((void**)&p_nm8,      g_nm8);
    cudaGetSymbolAddress((void**)&p_wt,       g_WT);
    cudaGetSymbolAddress((void**)&p_y,        g_Y);
    cudaGetSymbolAddress((void**)&p_wT,       g_wT);
    cudaGetSymbolAddress((void**)&p_xT,       g_xT);
    cudaGetSymbolAddress((void**)&p_common16, g_common16);

    cudaFuncSetAttribute(hmma_gemm<HEPI_OUT>, cudaFuncAttributeMaxDynamicSharedMemorySize, HSMEM_BYTES);
    cudaFuncSetAttribute(hmma_gemm<HEPI_Y>,   cudaFuncAttributeMaxDynamicSharedMemorySize, HSMEM_BYTES);
    cudaFuncSetAttribute(hmma_sim,            cudaFuncAttributeMaxDynamicSharedMemorySize, HSMEM_BYTES);
    cudaFuncSetAttribute(i8gemm_common,       cudaFuncAttributeMaxDynamicSharedMemorySize, I8SMEM_BYTES);

    // persistent side stream + events for fork-join capture (host handles only)
    static cudaStream_t sB = nullptr;
    static cudaEvent_t evFork = nullptr, evX = nullptr, evJoin = nullptr;
    if (sB == nullptr) {
        cudaStreamCreateWithFlags(&sB, cudaStreamNonBlocking);
        cudaEventCreateWithFlags(&evFork, cudaEventDisableTiming);
        cudaEventCreateWithFlags(&evX,    cudaEventDisableTiming);
        cudaEventCreateWithFlags(&evJoin, cudaEventDisableTiming);
    }

    // ---- fork: weight transpose on sB (depends only on weight) ----
    cudaEventRecord(evFork, 0);
    cudaStreamWaitEvent(sB, evFork, 0);
    {
        dim3 grid(TT / 32, TT / 32); dim3 blk(32, 32);
        k_wT<<<grid, blk, 0, sB>>>(weight);
    }

    // ---- default: fused x prep (mean + fp16 transpose, reads x once) ----
    {
        dim3 grid(NN / 32, TT / 32); dim3 blk(32, 32);
        k_xprep<<<grid, blk>>>(x);
    }
    cudaEventRecord(evX, 0);

    // ---- sB: Y GEMM (needs xT + wT) ----
    cudaStreamWaitEvent(sB, evX, 0);
    {
        // Y[(b,o)][n] = sum_t wT[o][t] * xT[b][n][t]   (1-term fp16, K=256)
        dim3 grid(NN / 128, TT / 128, BB);
        hmma_gemm<HEPI_Y><<<grid, 256, HSMEM_BYTES, sB>>>(
            p_wT, p_xT, nullptr, TT, TT, TT, NN,
            (size_t)NN * TT, TT, nullptr);
    }
    cudaEventRecord(evJoin, sB);

    // ---- adjacency chain on default stream ----
    k_colnorm<<<NN / 256, 256>>>();          // also zeroes g_deg64
    {
        dim3 grid(NN / 32, TT / 32); dim3 blk(32, 32);
        k_writenorm<<<grid, blk>>>();
    }

    // sim GEMM over lower-triangle blocks; epilogue emits adj (both dirs) + nmask
    {
        const int NTILES = (NN / 128) * (NN / 128 + 1) / 2;   // 136
        hmma_sim<<<NTILES, 256, HSMEM_BYTES>>>(p_xa3, p_xb3, gumbel);
    }

    // common = nm @ nm^T (lower-tri u16) + fused exact deg sums
    {
        const int NTILES = (NN / 128) * (NN / 128 + 1) / 2;   // 136
        i8gemm_common<<<NTILES, 256, I8SMEM_BYTES>>>(p_nm8, p_nm8, p_common16, NN, NN, NN, NN);
    }

    // WT = fp16(Wn^T), triangular 32-tile grid, both orientations; dinv inline
    {
        const int NTILES32 = (NN / 32) * (NN / 32 + 1) / 2;   // 2080
        dim3 blk(32, 32);
        k_wnT<<<NTILES32, blk>>>();
    }

    // ---- join: out GEMM needs g_Y (sB) + g_WT (default) ----
    cudaStreamWaitEvent(0, evJoin, 0);

    // out = Y @ Wn + bias  (single-term fp16, K=2048)
    {
        dim3 grid(NN / 128, (BB * TT) / 128);
        hmma_gemm<HEPI_OUT><<<grid, 256, HSMEM_BYTES>>>(
            p_y, p_wt, out, NN, NN, NN, NN, 0, 0, bias);
    }
}